// round 1
// baseline (speedup 1.0000x reference)
#include <cuda_runtime.h>
#include <math.h>

#define D_MODEL 1024
#define N_HEADS 16
#define HEAD_DIM 64
#define B_SZ 4
#define SEQ 2048
#define M_TOK (B_SZ * SEQ)   // 8192 tokens

// ---------------- scratch (static device globals; no allocation allowed) ----
__device__ float g_h   [(size_t)M_TOK * D_MODEL];       // normed activations (reused)
__device__ float g_qkv [(size_t)M_TOK * 3 * D_MODEL];   // qkv projections
__device__ float g_attn[(size_t)M_TOK * D_MODEL];       // attention output
__device__ float g_x1  [(size_t)M_TOK * D_MODEL];       // residual after attn
__device__ float g_ffn [(size_t)M_TOK * 4 * D_MODEL];   // fc1 output

// ---------------------------------------------------------------- RMSNorm ---
__global__ void rmsnorm_kernel(const float* __restrict__ x,
                               const float* __restrict__ scale,
                               float* __restrict__ out) {
    int row = blockIdx.x;
    int t = threadIdx.x;  // 256 threads, D=1024 -> one float4 per thread
    const float4* xr = reinterpret_cast<const float4*>(x + (size_t)row * D_MODEL);
    float4 v = xr[t];
    float ss = v.x * v.x + v.y * v.y + v.z * v.z + v.w * v.w;
    #pragma unroll
    for (int o = 16; o > 0; o >>= 1) ss += __shfl_xor_sync(0xffffffffu, ss, o);
    __shared__ float wsum[8];
    if ((t & 31) == 0) wsum[t >> 5] = ss;
    __syncthreads();
    if (t < 8) {
        float s2 = wsum[t];
        #pragma unroll
        for (int o = 4; o > 0; o >>= 1) s2 += __shfl_xor_sync(0xffu, s2, o);
        if (t == 0) wsum[0] = s2;
    }
    __syncthreads();
    float inv = rsqrtf(wsum[0] * (1.0f / D_MODEL) + 1e-8f);
    float4 s4 = reinterpret_cast<const float4*>(scale)[t];
    float4 o4 = make_float4(v.x * inv * s4.x, v.y * inv * s4.y,
                            v.z * inv * s4.z, v.w * inv * s4.w);
    reinterpret_cast<float4*>(out + (size_t)row * D_MODEL)[t] = o4;
}

// ---------------------------------------------------------------- SGEMM -----
// C[M,N] = A[M,K] @ B[K,N]  (+ residual / GELU per EPI)
// EPI: 0 = none, 1 = C = R + A@B, 2 = C = gelu_exact(A@B)
__device__ __forceinline__ float gelu_exact(float v) {
    return 0.5f * v * (1.0f + erff(v * 0.70710678118654752f));
}

template <int EPI>
__global__ __launch_bounds__(256, 2)
void sgemm_kernel(const float* __restrict__ A, const float* __restrict__ Bm,
                  const float* __restrict__ R, float* __restrict__ C,
                  int M, int N, int K) {
    __shared__ float As[8][128];   // [k][m]
    __shared__ float Bs[8][128];   // [k][n]
    int tid = threadIdx.x;
    int bm = blockIdx.y * 128, bn = blockIdx.x * 128;
    int ty = tid >> 4, tx = tid & 15;

    float c[8][8] = {};

    int arow = tid >> 1;            // 0..127
    int acol = (tid & 1) * 4;       // 0 or 4
    int brow = tid >> 5;            // 0..7
    int bcol = (tid & 31) * 4;      // 0..124

    const float* Aptr = A + (size_t)(bm + arow) * K + acol;
    const float* Bptr = Bm + (size_t)brow * N + bn + bcol;

    for (int k0 = 0; k0 < K; k0 += 8) {
        float4 av = *reinterpret_cast<const float4*>(Aptr + k0);
        float4 bv = *reinterpret_cast<const float4*>(Bptr + (size_t)k0 * N);
        As[acol + 0][arow] = av.x;
        As[acol + 1][arow] = av.y;
        As[acol + 2][arow] = av.z;
        As[acol + 3][arow] = av.w;
        *reinterpret_cast<float4*>(&Bs[brow][bcol]) = bv;
        __syncthreads();
        #pragma unroll
        for (int k = 0; k < 8; k++) {
            float a[8], b[8];
            *(float4*)(a)     = *(float4*)&As[k][ty * 8];
            *(float4*)(a + 4) = *(float4*)&As[k][ty * 8 + 4];
            *(float4*)(b)     = *(float4*)&Bs[k][tx * 8];
            *(float4*)(b + 4) = *(float4*)&Bs[k][tx * 8 + 4];
            #pragma unroll
            for (int i = 0; i < 8; i++)
                #pragma unroll
                for (int j = 0; j < 8; j++)
                    c[i][j] += a[i] * b[j];
        }
        __syncthreads();
    }

    #pragma unroll
    for (int i = 0; i < 8; i++) {
        int row = bm + ty * 8 + i;
        float* Crow = C + (size_t)row * N + bn + tx * 8;
        const float* Rrow = (EPI == 1) ? (R + (size_t)row * N + bn + tx * 8) : nullptr;
        #pragma unroll
        for (int j = 0; j < 8; j += 4) {
            float4 v = make_float4(c[i][j], c[i][j + 1], c[i][j + 2], c[i][j + 3]);
            if (EPI == 2) {
                v.x = gelu_exact(v.x); v.y = gelu_exact(v.y);
                v.z = gelu_exact(v.z); v.w = gelu_exact(v.w);
            }
            if (EPI == 1) {
                float4 r = *reinterpret_cast<const float4*>(Rrow + j);
                v.x += r.x; v.y += r.y; v.z += r.z; v.w += r.w;
            }
            *reinterpret_cast<float4*>(Crow + j) = v;
        }
    }
}

// ------------------------------------------------------------- Attention ----
// Flash-style: grid (SEQ/64, B*H); block 256 threads (16x16), each thread a
// 4q x 4(k|d) microtile. Q/K stored transposed [d][row] for conflict-free
// float4 fragment loads; P reuses the K buffer (48KB total static smem).
__global__ __launch_bounds__(256, 2)
void attn_kernel(const float* __restrict__ qkv, float* __restrict__ out) {
    __shared__ float Qt[64][64];   // [d][q]
    __shared__ float KP[64][64];   // K as [d][k], then P as [k][q]
    __shared__ float Vs[64][64];   // [k][d]

    int bh = blockIdx.y;
    int b = bh >> 4, h = bh & 15;
    int q0 = blockIdx.x * 64;
    int tid = threadIdx.x;
    int ty = tid >> 4, tx = tid & 15;

    const size_t rs = 3 * D_MODEL;
    const float* qbase = qkv + (size_t)b * SEQ * rs + h * HEAD_DIM;
    const float* kbase = qbase + D_MODEL;
    const float* vbase = qbase + 2 * D_MODEL;

    // load Q tile transposed
    for (int i = tid; i < 64 * 16; i += 256) {
        int r = i >> 4, c4 = (i & 15) * 4;
        float4 v = *reinterpret_cast<const float4*>(qbase + (size_t)(q0 + r) * rs + c4);
        Qt[c4 + 0][r] = v.x; Qt[c4 + 1][r] = v.y;
        Qt[c4 + 2][r] = v.z; Qt[c4 + 3][r] = v.w;
    }

    float o[4][4] = {};
    float mrow[4], lrow[4];
    #pragma unroll
    for (int i = 0; i < 4; i++) { mrow[i] = -1e30f; lrow[i] = 0.0f; }

    for (int k0 = 0; k0 < SEQ; k0 += 64) {
        __syncthreads();  // prev-iter consumers of KP/Vs done
        for (int i = tid; i < 64 * 16; i += 256) {
            int r = i >> 4, c4 = (i & 15) * 4;
            float4 kv = *reinterpret_cast<const float4*>(kbase + (size_t)(k0 + r) * rs + c4);
            KP[c4 + 0][r] = kv.x; KP[c4 + 1][r] = kv.y;
            KP[c4 + 2][r] = kv.z; KP[c4 + 3][r] = kv.w;
            float4 vv = *reinterpret_cast<const float4*>(vbase + (size_t)(k0 + r) * rs + c4);
            *reinterpret_cast<float4*>(&Vs[r][c4]) = vv;
        }
        __syncthreads();

        // S = Q K^T (scaled)
        float s[4][4] = {};
        #pragma unroll
        for (int d = 0; d < 64; d++) {
            float a[4], bb[4];
            *(float4*)a  = *(float4*)&Qt[d][ty * 4];
            *(float4*)bb = *(float4*)&KP[d][tx * 4];
            #pragma unroll
            for (int i = 0; i < 4; i++)
                #pragma unroll
                for (int j = 0; j < 4; j++)
                    s[i][j] += a[i] * bb[j];
        }

        // online softmax (row reductions over the 16 tx lanes; lane bits 0..3)
        #pragma unroll
        for (int i = 0; i < 4; i++) {
            float mx = -1e30f;
            #pragma unroll
            for (int j = 0; j < 4; j++) { s[i][j] *= 0.125f; mx = fmaxf(mx, s[i][j]); }
            #pragma unroll
            for (int off = 8; off > 0; off >>= 1)
                mx = fmaxf(mx, __shfl_xor_sync(0xffffffffu, mx, off));
            float mn = fmaxf(mrow[i], mx);
            float al = __expf(mrow[i] - mn);
            float rsum = 0.0f;
            #pragma unroll
            for (int j = 0; j < 4; j++) {
                float p = __expf(s[i][j] - mn);
                s[i][j] = p;
                rsum += p;
            }
            #pragma unroll
            for (int off = 8; off > 0; off >>= 1)
                rsum += __shfl_xor_sync(0xffffffffu, rsum, off);
            lrow[i] = lrow[i] * al + rsum;
            mrow[i] = mn;
            #pragma unroll
            for (int j = 0; j < 4; j++) o[i][j] *= al;
        }

        __syncthreads();  // all threads done reading KP as K
        #pragma unroll
        for (int i = 0; i < 4; i++)
            #pragma unroll
            for (int j = 0; j < 4; j++)
                KP[tx * 4 + j][ty * 4 + i] = s[i][j];  // P^T: [k][q]
        __syncthreads();

        // O += P @ V
        #pragma unroll
        for (int kk = 0; kk < 64; kk++) {
            float pa[4], vb[4];
            *(float4*)pa = *(float4*)&KP[kk][ty * 4];
            *(float4*)vb = *(float4*)&Vs[kk][tx * 4];
            #pragma unroll
            for (int i = 0; i < 4; i++)
                #pragma unroll
                for (int j = 0; j < 4; j++)
                    o[i][j] += pa[i] * vb[j];
        }
    }

    #pragma unroll
    for (int i = 0; i < 4; i++) {
        float invl = 1.0f / lrow[i];
        int row = q0 + ty * 4 + i;
        float4 ov = make_float4(o[i][0] * invl, o[i][1] * invl,
                                o[i][2] * invl, o[i][3] * invl);
        *reinterpret_cast<float4*>(
            &out[((size_t)(b * SEQ + row)) * D_MODEL + h * HEAD_DIM + tx * 4]) = ov;
    }
}

// ---------------------------------------------------------------- launch ----
extern "C" void kernel_launch(void* const* d_in, const int* in_sizes, int n_in,
                              void* d_out, int out_size) {
    const float* x     = (const float*)d_in[0];
    const float* n1    = (const float*)d_in[1];
    const float* wqkv  = (const float*)d_in[2];
    const float* wproj = (const float*)d_in[3];
    const float* n2    = (const float*)d_in[4];
    const float* wfc1  = (const float*)d_in[5];
    const float* wfc2  = (const float*)d_in[6];
    float* out = (float*)d_out;

    float *p_h, *p_qkv, *p_attn, *p_x1, *p_ffn;
    cudaGetSymbolAddress((void**)&p_h,    g_h);
    cudaGetSymbolAddress((void**)&p_qkv,  g_qkv);
    cudaGetSymbolAddress((void**)&p_attn, g_attn);
    cudaGetSymbolAddress((void**)&p_x1,   g_x1);
    cudaGetSymbolAddress((void**)&p_ffn,  g_ffn);

    dim3 blk(256);

    // h = rmsnorm(x, norm1_scale)
    rmsnorm_kernel<<<M_TOK, blk>>>(x, n1, p_h);

    // qkv = h @ w_qkv   [8192,1024]x[1024,3072]
    sgemm_kernel<0><<<dim3(3 * D_MODEL / 128, M_TOK / 128), blk>>>(
        p_h, wqkv, nullptr, p_qkv, M_TOK, 3 * D_MODEL, D_MODEL);

    // attention
    attn_kernel<<<dim3(SEQ / 64, B_SZ * N_HEADS), blk>>>(p_qkv, p_attn);

    // x1 = x + attn_out @ w_proj
    sgemm_kernel<1><<<dim3(D_MODEL / 128, M_TOK / 128), blk>>>(
        p_attn, wproj, x, p_x1, M_TOK, D_MODEL, D_MODEL);

    // h = rmsnorm(x1, norm2_scale)
    rmsnorm_kernel<<<M_TOK, blk>>>(p_x1, n2, p_h);

    // ffn = gelu(h @ w_fc1)   [8192,1024]x[1024,4096]
    sgemm_kernel<2><<<dim3(4 * D_MODEL / 128, M_TOK / 128), blk>>>(
        p_h, wfc1, nullptr, p_ffn, M_TOK, 4 * D_MODEL, D_MODEL);

    // out = x1 + ffn @ w_fc2  [8192,4096]x[4096,1024]
    sgemm_kernel<1><<<dim3(D_MODEL / 128, M_TOK / 128), blk>>>(
        p_ffn, wfc2, p_x1, out, M_TOK, D_MODEL, 4 * D_MODEL);
}

// round 2
// speedup vs baseline: 2.9635x; 2.9635x over previous
#include <cuda_runtime.h>
#include <math.h>
#include <stdint.h>

#define D_MODEL 1024
#define N_HEADS 16
#define HEAD_DIM 64
#define B_SZ 4
#define SEQ 2048
#define M_TOK (B_SZ * SEQ)   // 8192 tokens

// ---------------- scratch (static device globals; no allocation allowed) ----
__device__ float g_h   [(size_t)M_TOK * D_MODEL];
__device__ float g_qkv [(size_t)M_TOK * 3 * D_MODEL];
__device__ float g_attn[(size_t)M_TOK * D_MODEL];
__device__ float g_x1  [(size_t)M_TOK * D_MODEL];
__device__ float g_ffn [(size_t)M_TOK * 4 * D_MODEL];

// ---------------------------------------------------------------- RMSNorm ---
__global__ void rmsnorm_kernel(const float* __restrict__ x,
                               const float* __restrict__ scale,
                               float* __restrict__ out) {
    int row = blockIdx.x;
    int t = threadIdx.x;
    const float4* xr = reinterpret_cast<const float4*>(x + (size_t)row * D_MODEL);
    float4 v = xr[t];
    float ss = v.x * v.x + v.y * v.y + v.z * v.z + v.w * v.w;
    #pragma unroll
    for (int o = 16; o > 0; o >>= 1) ss += __shfl_xor_sync(0xffffffffu, ss, o);
    __shared__ float wsum[8];
    if ((t & 31) == 0) wsum[t >> 5] = ss;
    __syncthreads();
    if (t < 8) {
        float s2 = wsum[t];
        #pragma unroll
        for (int o = 4; o > 0; o >>= 1) s2 += __shfl_xor_sync(0xffu, s2, o);
        if (t == 0) wsum[0] = s2;
    }
    __syncthreads();
    float inv = rsqrtf(wsum[0] * (1.0f / D_MODEL) + 1e-8f);
    float4 s4 = reinterpret_cast<const float4*>(scale)[t];
    float4 o4 = make_float4(v.x * inv * s4.x, v.y * inv * s4.y,
                            v.z * inv * s4.z, v.w * inv * s4.w);
    reinterpret_cast<float4*>(out + (size_t)row * D_MODEL)[t] = o4;
}

// ------------------------------------------------------- TF32 tensor GEMM ---
// C[M,N] = A[M,K] @ B[K,N] via mma.sync.m16n8k8 tf32.
// CTA tile 128x128xBK16, 8 warps (2x4), warp tile 64x32, cp.async 2-stage.
#define BMT 128
#define BNT 128
#define BKT 16
#define ASTR 20    // A smem row stride (floats); banks (20m+k)%32 all-distinct
#define BSTR 136   // B smem row stride (floats); banks (8k+n)%32 all-distinct

__device__ __forceinline__ uint32_t f2tf32(float x) {
    uint32_t r;
    asm("cvt.rna.tf32.f32 %0, %1;" : "=r"(r) : "f"(x));
    return r;
}
__device__ __forceinline__ void mma_tf32(float* c, const uint32_t* a, const uint32_t* b) {
    asm volatile(
        "mma.sync.aligned.m16n8k8.row.col.f32.tf32.tf32.f32 "
        "{%0,%1,%2,%3}, {%4,%5,%6,%7}, {%8,%9}, {%0,%1,%2,%3};"
        : "+f"(c[0]), "+f"(c[1]), "+f"(c[2]), "+f"(c[3])
        : "r"(a[0]), "r"(a[1]), "r"(a[2]), "r"(a[3]), "r"(b[0]), "r"(b[1]));
}
__device__ __forceinline__ void cp_async16(uint32_t smem, const void* gmem) {
    asm volatile("cp.async.cg.shared.global [%0], [%1], 16;\n" ::"r"(smem), "l"(gmem));
}
__device__ __forceinline__ float gelu_exact(float v) {
    return 0.5f * v * (1.0f + erff(v * 0.70710678118654752f));
}

// EPI: 0 = none, 1 = C = R + A@B, 2 = C = gelu_exact(A@B)
template <int EPI>
__global__ __launch_bounds__(256)
void tgemm_kernel(const float* __restrict__ A, const float* __restrict__ Bm,
                  const float* __restrict__ R, float* __restrict__ C,
                  int M, int N, int K) {
    __shared__ float As[2][BMT * ASTR];
    __shared__ float Bs[2][BKT * BSTR];

    int tid = threadIdx.x;
    int warp = tid >> 5, lane = tid & 31;
    int group = lane >> 2, tig = lane & 3;
    int wm = warp >> 2, wn = warp & 3;      // 2 x 4 warp grid
    int bm = blockIdx.y * BMT, bn = blockIdx.x * BNT;

    uint32_t sA[2], sB[2];
    sA[0] = (uint32_t)__cvta_generic_to_shared(&As[0][0]);
    sA[1] = (uint32_t)__cvta_generic_to_shared(&As[1][0]);
    sB[0] = (uint32_t)__cvta_generic_to_shared(&Bs[0][0]);
    sB[1] = (uint32_t)__cvta_generic_to_shared(&Bs[1][0]);

    // per-thread copy coordinates (2 chunks of 16B each for A and B)
    // A: 128 rows x 4 chunks ; B: 16 rows x 32 chunks
    int a_row0 = tid >> 2, a_c0 = (tid & 3) * 4;              // chunk tid
    int a_row1 = (tid + 256) >> 2, a_c1 = ((tid + 256) & 3) * 4;
    int b_row0 = tid >> 5, b_c0 = (tid & 31) * 4;
    int b_row1 = (tid + 256) >> 5, b_c1 = ((tid + 256) & 31) * 4;

    auto load_stage = [&](int s, int k0) {
        cp_async16(sA[s] + (uint32_t)(a_row0 * ASTR + a_c0) * 4,
                   A + (size_t)(bm + a_row0) * K + k0 + a_c0);
        cp_async16(sA[s] + (uint32_t)(a_row1 * ASTR + a_c1) * 4,
                   A + (size_t)(bm + a_row1) * K + k0 + a_c1);
        cp_async16(sB[s] + (uint32_t)(b_row0 * BSTR + b_c0) * 4,
                   Bm + (size_t)(k0 + b_row0) * N + bn + b_c0);
        cp_async16(sB[s] + (uint32_t)(b_row1 * BSTR + b_c1) * 4,
                   Bm + (size_t)(k0 + b_row1) * N + bn + b_c1);
        asm volatile("cp.async.commit_group;\n" ::);
    };

    float c[4][4][4] = {};   // [mt][nt][frag]

    int KT = K / BKT;
    load_stage(0, 0);

    for (int kt = 0; kt < KT; kt++) {
        asm volatile("cp.async.wait_group 0;\n" ::);
        __syncthreads();
        if (kt + 1 < KT) load_stage((kt + 1) & 1, (kt + 1) * BKT);
        int s = kt & 1;

        #pragma unroll
        for (int ks = 0; ks < BKT; ks += 8) {
            uint32_t af[4][4], bf[4][2];
            #pragma unroll
            for (int mt = 0; mt < 4; mt++) {
                int m = wm * 64 + mt * 16 + group;
                const float* base = &As[s][0];
                af[mt][0] = f2tf32(base[(m)     * ASTR + ks + tig]);
                af[mt][1] = f2tf32(base[(m + 8) * ASTR + ks + tig]);
                af[mt][2] = f2tf32(base[(m)     * ASTR + ks + tig + 4]);
                af[mt][3] = f2tf32(base[(m + 8) * ASTR + ks + tig + 4]);
            }
            #pragma unroll
            for (int nt = 0; nt < 4; nt++) {
                int n = wn * 32 + nt * 8 + group;
                const float* base = &Bs[s][0];
                bf[nt][0] = f2tf32(base[(ks + tig)     * BSTR + n]);
                bf[nt][1] = f2tf32(base[(ks + tig + 4) * BSTR + n]);
            }
            #pragma unroll
            for (int mt = 0; mt < 4; mt++)
                #pragma unroll
                for (int nt = 0; nt < 4; nt++)
                    mma_tf32(c[mt][nt], af[mt], bf[nt]);
        }
        __syncthreads();
    }

    // ---- epilogue: c frag (row=group(+8), col=2*tig(+1)) -> float2 stores
    #pragma unroll
    for (int mt = 0; mt < 4; mt++) {
        #pragma unroll
        for (int half = 0; half < 2; half++) {
            int row = bm + wm * 64 + mt * 16 + group + half * 8;
            float* Crow = C + (size_t)row * N;
            const float* Rrow = (EPI == 1) ? (R + (size_t)row * N) : nullptr;
            #pragma unroll
            for (int nt = 0; nt < 4; nt++) {
                int col = bn + wn * 32 + nt * 8 + tig * 2;
                float v0 = c[mt][nt][half * 2 + 0];
                float v1 = c[mt][nt][half * 2 + 1];
                if (EPI == 2) { v0 = gelu_exact(v0); v1 = gelu_exact(v1); }
                if (EPI == 1) {
                    float2 r2 = *reinterpret_cast<const float2*>(Rrow + col);
                    v0 += r2.x; v1 += r2.y;
                }
                *reinterpret_cast<float2*>(Crow + col) = make_float2(v0, v1);
            }
        }
    }
}

// ------------------------------------------------------------- Attention ----
__global__ __launch_bounds__(256, 2)
void attn_kernel(const float* __restrict__ qkv, float* __restrict__ out) {
    __shared__ float Qt[64][64];
    __shared__ float KP[64][64];
    __shared__ float Vs[64][64];

    int bh = blockIdx.y;
    int b = bh >> 4, h = bh & 15;
    int q0 = blockIdx.x * 64;
    int tid = threadIdx.x;
    int ty = tid >> 4, tx = tid & 15;

    const size_t rs = 3 * D_MODEL;
    const float* qbase = qkv + (size_t)b * SEQ * rs + h * HEAD_DIM;
    const float* kbase = qbase + D_MODEL;
    const float* vbase = qbase + 2 * D_MODEL;

    for (int i = tid; i < 64 * 16; i += 256) {
        int r = i >> 4, c4 = (i & 15) * 4;
        float4 v = *reinterpret_cast<const float4*>(qbase + (size_t)(q0 + r) * rs + c4);
        Qt[c4 + 0][r] = v.x; Qt[c4 + 1][r] = v.y;
        Qt[c4 + 2][r] = v.z; Qt[c4 + 3][r] = v.w;
    }

    float o[4][4] = {};
    float mrow[4], lrow[4];
    #pragma unroll
    for (int i = 0; i < 4; i++) { mrow[i] = -1e30f; lrow[i] = 0.0f; }

    for (int k0 = 0; k0 < SEQ; k0 += 64) {
        __syncthreads();
        for (int i = tid; i < 64 * 16; i += 256) {
            int r = i >> 4, c4 = (i & 15) * 4;
            float4 kv = *reinterpret_cast<const float4*>(kbase + (size_t)(k0 + r) * rs + c4);
            KP[c4 + 0][r] = kv.x; KP[c4 + 1][r] = kv.y;
            KP[c4 + 2][r] = kv.z; KP[c4 + 3][r] = kv.w;
            float4 vv = *reinterpret_cast<const float4*>(vbase + (size_t)(k0 + r) * rs + c4);
            *reinterpret_cast<float4*>(&Vs[r][c4]) = vv;
        }
        __syncthreads();

        float s[4][4] = {};
        #pragma unroll
        for (int d = 0; d < 64; d++) {
            float a[4], bb[4];
            *(float4*)a  = *(float4*)&Qt[d][ty * 4];
            *(float4*)bb = *(float4*)&KP[d][tx * 4];
            #pragma unroll
            for (int i = 0; i < 4; i++)
                #pragma unroll
                for (int j = 0; j < 4; j++)
                    s[i][j] += a[i] * bb[j];
        }

        #pragma unroll
        for (int i = 0; i < 4; i++) {
            float mx = -1e30f;
            #pragma unroll
            for (int j = 0; j < 4; j++) { s[i][j] *= 0.125f; mx = fmaxf(mx, s[i][j]); }
            #pragma unroll
            for (int off = 8; off > 0; off >>= 1)
                mx = fmaxf(mx, __shfl_xor_sync(0xffffffffu, mx, off));
            float mn = fmaxf(mrow[i], mx);
            float al = __expf(mrow[i] - mn);
            float rsum = 0.0f;
            #pragma unroll
            for (int j = 0; j < 4; j++) {
                float p = __expf(s[i][j] - mn);
                s[i][j] = p;
                rsum += p;
            }
            #pragma unroll
            for (int off = 8; off > 0; off >>= 1)
                rsum += __shfl_xor_sync(0xffffffffu, rsum, off);
            lrow[i] = lrow[i] * al + rsum;
            mrow[i] = mn;
            #pragma unroll
            for (int j = 0; j < 4; j++) o[i][j] *= al;
        }

        __syncthreads();
        #pragma unroll
        for (int i = 0; i < 4; i++)
            #pragma unroll
            for (int j = 0; j < 4; j++)
                KP[tx * 4 + j][ty * 4 + i] = s[i][j];
        __syncthreads();

        #pragma unroll
        for (int kk = 0; kk < 64; kk++) {
            float pa[4], vb[4];
            *(float4*)pa = *(float4*)&KP[kk][ty * 4];
            *(float4*)vb = *(float4*)&Vs[kk][tx * 4];
            #pragma unroll
            for (int i = 0; i < 4; i++)
                #pragma unroll
                for (int j = 0; j < 4; j++)
                    o[i][j] += pa[i] * vb[j];
        }
    }

    #pragma unroll
    for (int i = 0; i < 4; i++) {
        float invl = 1.0f / lrow[i];
        int row = q0 + ty * 4 + i;
        float4 ov = make_float4(o[i][0] * invl, o[i][1] * invl,
                                o[i][2] * invl, o[i][3] * invl);
        *reinterpret_cast<float4*>(
            &out[((size_t)(b * SEQ + row)) * D_MODEL + h * HEAD_DIM + tx * 4]) = ov;
    }
}

// ---------------------------------------------------------------- launch ----
extern "C" void kernel_launch(void* const* d_in, const int* in_sizes, int n_in,
                              void* d_out, int out_size) {
    const float* x     = (const float*)d_in[0];
    const float* n1    = (const float*)d_in[1];
    const float* wqkv  = (const float*)d_in[2];
    const float* wproj = (const float*)d_in[3];
    const float* n2    = (const float*)d_in[4];
    const float* wfc1  = (const float*)d_in[5];
    const float* wfc2  = (const float*)d_in[6];
    float* out = (float*)d_out;

    float *p_h, *p_qkv, *p_attn, *p_x1, *p_ffn;
    cudaGetSymbolAddress((void**)&p_h,    g_h);
    cudaGetSymbolAddress((void**)&p_qkv,  g_qkv);
    cudaGetSymbolAddress((void**)&p_attn, g_attn);
    cudaGetSymbolAddress((void**)&p_x1,   g_x1);
    cudaGetSymbolAddress((void**)&p_ffn,  g_ffn);

    dim3 blk(256);

    rmsnorm_kernel<<<M_TOK, blk>>>(x, n1, p_h);

    tgemm_kernel<0><<<dim3(3 * D_MODEL / BNT, M_TOK / BMT), blk>>>(
        p_h, wqkv, nullptr, p_qkv, M_TOK, 3 * D_MODEL, D_MODEL);

    attn_kernel<<<dim3(SEQ / 64, B_SZ * N_HEADS), blk>>>(p_qkv, p_attn);

    tgemm_kernel<1><<<dim3(D_MODEL / BNT, M_TOK / BMT), blk>>>(
        p_attn, wproj, x, p_x1, M_TOK, D_MODEL, D_MODEL);

    rmsnorm_kernel<<<M_TOK, blk>>>(p_x1, n2, p_h);

    tgemm_kernel<2><<<dim3(4 * D_MODEL / BNT, M_TOK / BMT), blk>>>(
        p_h, wfc1, nullptr, p_ffn, M_TOK, 4 * D_MODEL, D_MODEL);

    tgemm_kernel<1><<<dim3(D_MODEL / BNT, M_TOK / BMT), blk>>>(
        p_ffn, wfc2, p_x1, out, M_TOK, D_MODEL, 4 * D_MODEL);
}

// round 3
// speedup vs baseline: 4.7077x; 1.5885x over previous
#include <cuda_runtime.h>
#include <math.h>
#include <stdint.h>

#define D_MODEL 1024
#define N_HEADS 16
#define HEAD_DIM 64
#define B_SZ 4
#define SEQ 2048
#define M_TOK (B_SZ * SEQ)

// ---------------- scratch ----------------
__device__ float g_h   [(size_t)M_TOK * D_MODEL];
__device__ float g_qkv [(size_t)M_TOK * 3 * D_MODEL];
__device__ float g_attn[(size_t)M_TOK * D_MODEL];
__device__ float g_x1  [(size_t)M_TOK * D_MODEL];
__device__ float g_ffn [(size_t)M_TOK * 4 * D_MODEL];

// ---------------------------------------------------------------- RMSNorm ---
__global__ void rmsnorm_kernel(const float* __restrict__ x,
                               const float* __restrict__ scale,
                               float* __restrict__ out) {
    int row = blockIdx.x;
    int t = threadIdx.x;
    const float4* xr = reinterpret_cast<const float4*>(x + (size_t)row * D_MODEL);
    float4 v = xr[t];
    float ss = v.x * v.x + v.y * v.y + v.z * v.z + v.w * v.w;
    #pragma unroll
    for (int o = 16; o > 0; o >>= 1) ss += __shfl_xor_sync(0xffffffffu, ss, o);
    __shared__ float wsum[8];
    if ((t & 31) == 0) wsum[t >> 5] = ss;
    __syncthreads();
    if (t < 8) {
        float s2 = wsum[t];
        #pragma unroll
        for (int o = 4; o > 0; o >>= 1) s2 += __shfl_xor_sync(0xffu, s2, o);
        if (t == 0) wsum[0] = s2;
    }
    __syncthreads();
    float inv = rsqrtf(wsum[0] * (1.0f / D_MODEL) + 1e-8f);
    float4 s4 = reinterpret_cast<const float4*>(scale)[t];
    float4 o4 = make_float4(v.x * inv * s4.x, v.y * inv * s4.y,
                            v.z * inv * s4.z, v.w * inv * s4.w);
    reinterpret_cast<float4*>(out + (size_t)row * D_MODEL)[t] = o4;
}

// ------------------------------------------------------- common tf32 bits ---
__device__ __forceinline__ uint32_t f2tf32(float x) {
    uint32_t r;
    asm("cvt.rna.tf32.f32 %0, %1;" : "=r"(r) : "f"(x));
    return r;
}
__device__ __forceinline__ void mma_tf32(float* c, const uint32_t* a, const uint32_t* b) {
    asm volatile(
        "mma.sync.aligned.m16n8k8.row.col.f32.tf32.tf32.f32 "
        "{%0,%1,%2,%3}, {%4,%5,%6,%7}, {%8,%9}, {%0,%1,%2,%3};"
        : "+f"(c[0]), "+f"(c[1]), "+f"(c[2]), "+f"(c[3])
        : "r"(a[0]), "r"(a[1]), "r"(a[2]), "r"(a[3]), "r"(b[0]), "r"(b[1]));
}
__device__ __forceinline__ void cp_async16(uint32_t smem, const void* gmem) {
    asm volatile("cp.async.cg.shared.global [%0], [%1], 16;\n" ::"r"(smem), "l"(gmem));
}
__device__ __forceinline__ float gelu_exact(float v) {
    return 0.5f * v * (1.0f + erff(v * 0.70710678118654752f));
}

// ------------------------------------------------------- TF32 tensor GEMM ---
#define BMT 128
#define BNT 128
#define BKT 16
#define ASTR 20
#define BSTR 136

template <int EPI>  // 0 none, 1 +residual, 2 gelu
__global__ __launch_bounds__(256)
void tgemm_kernel(const float* __restrict__ A, const float* __restrict__ Bm,
                  const float* __restrict__ R, float* __restrict__ C,
                  int M, int N, int K) {
    __shared__ float As[2][BMT * ASTR];
    __shared__ float Bs[2][BKT * BSTR];

    int tid = threadIdx.x;
    int warp = tid >> 5, lane = tid & 31;
    int group = lane >> 2, tig = lane & 3;
    int wm = warp >> 2, wn = warp & 3;
    int bm = blockIdx.y * BMT, bn = blockIdx.x * BNT;

    uint32_t sA[2], sB[2];
    sA[0] = (uint32_t)__cvta_generic_to_shared(&As[0][0]);
    sA[1] = (uint32_t)__cvta_generic_to_shared(&As[1][0]);
    sB[0] = (uint32_t)__cvta_generic_to_shared(&Bs[0][0]);
    sB[1] = (uint32_t)__cvta_generic_to_shared(&Bs[1][0]);

    int a_row0 = tid >> 2, a_c0 = (tid & 3) * 4;
    int a_row1 = (tid + 256) >> 2, a_c1 = ((tid + 256) & 3) * 4;
    int b_row0 = tid >> 5, b_c0 = (tid & 31) * 4;
    int b_row1 = (tid + 256) >> 5, b_c1 = ((tid + 256) & 31) * 4;

    auto load_stage = [&](int s, int k0) {
        cp_async16(sA[s] + (uint32_t)(a_row0 * ASTR + a_c0) * 4,
                   A + (size_t)(bm + a_row0) * K + k0 + a_c0);
        cp_async16(sA[s] + (uint32_t)(a_row1 * ASTR + a_c1) * 4,
                   A + (size_t)(bm + a_row1) * K + k0 + a_c1);
        cp_async16(sB[s] + (uint32_t)(b_row0 * BSTR + b_c0) * 4,
                   Bm + (size_t)(k0 + b_row0) * N + bn + b_c0);
        cp_async16(sB[s] + (uint32_t)(b_row1 * BSTR + b_c1) * 4,
                   Bm + (size_t)(k0 + b_row1) * N + bn + b_c1);
        asm volatile("cp.async.commit_group;\n" ::);
    };
    auto cvt4 = [&](float* p) {
        float4 v = *reinterpret_cast<float4*>(p);
        uint4 u;
        u.x = f2tf32(v.x); u.y = f2tf32(v.y); u.z = f2tf32(v.z); u.w = f2tf32(v.w);
        *reinterpret_cast<uint4*>(p) = u;
    };

    float c[4][4][4] = {};
    int KT = K / BKT;
    load_stage(0, 0);

    for (int kt = 0; kt < KT; kt++) {
        asm volatile("cp.async.wait_group 0;\n" ::);
        __syncthreads();
        if (kt + 1 < KT) load_stage((kt + 1) & 1, (kt + 1) * BKT);
        int s = kt & 1;
        // in-place tf32 conversion of this thread's own staged chunks
        cvt4(&As[s][a_row0 * ASTR + a_c0]);
        cvt4(&As[s][a_row1 * ASTR + a_c1]);
        cvt4(&Bs[s][b_row0 * BSTR + b_c0]);
        cvt4(&Bs[s][b_row1 * BSTR + b_c1]);
        __syncthreads();

        #pragma unroll
        for (int ks = 0; ks < BKT; ks += 8) {
            uint32_t af[4][4], bf[4][2];
            #pragma unroll
            for (int mt = 0; mt < 4; mt++) {
                int m = wm * 64 + mt * 16 + group;
                const float* base = &As[s][0];
                af[mt][0] = __float_as_uint(base[(m)     * ASTR + ks + tig]);
                af[mt][1] = __float_as_uint(base[(m + 8) * ASTR + ks + tig]);
                af[mt][2] = __float_as_uint(base[(m)     * ASTR + ks + tig + 4]);
                af[mt][3] = __float_as_uint(base[(m + 8) * ASTR + ks + tig + 4]);
            }
            #pragma unroll
            for (int nt = 0; nt < 4; nt++) {
                int n = wn * 32 + nt * 8 + group;
                const float* base = &Bs[s][0];
                bf[nt][0] = __float_as_uint(base[(ks + tig)     * BSTR + n]);
                bf[nt][1] = __float_as_uint(base[(ks + tig + 4) * BSTR + n]);
            }
            #pragma unroll
            for (int mt = 0; mt < 4; mt++)
                #pragma unroll
                for (int nt = 0; nt < 4; nt++)
                    mma_tf32(c[mt][nt], af[mt], bf[nt]);
        }
        __syncthreads();
    }

    #pragma unroll
    for (int mt = 0; mt < 4; mt++) {
        #pragma unroll
        for (int half = 0; half < 2; half++) {
            int row = bm + wm * 64 + mt * 16 + group + half * 8;
            float* Crow = C + (size_t)row * N;
            const float* Rrow = (EPI == 1) ? (R + (size_t)row * N) : nullptr;
            #pragma unroll
            for (int nt = 0; nt < 4; nt++) {
                int col = bn + wn * 32 + nt * 8 + tig * 2;
                float v0 = c[mt][nt][half * 2 + 0];
                float v1 = c[mt][nt][half * 2 + 1];
                if (EPI == 2) { v0 = gelu_exact(v0); v1 = gelu_exact(v1); }
                if (EPI == 1) {
                    float2 r2 = *reinterpret_cast<const float2*>(Rrow + col);
                    v0 += r2.x; v1 += r2.y;
                }
                *reinterpret_cast<float2*>(Crow + col) = make_float2(v0, v1);
            }
        }
    }
}

// ----------------------------------------- TF32 tensor flash attention -----
// block: 128 threads (4 warps), q-tile 64 (warp = 16q x 64k), k-tile 64.
// KPs holds K (tf32, [k][d], stride 68) then P (tf32, [q][k], stride 68).
// Vs holds V (tf32, [k][d], stride 72).
#define KSTR 68
#define VSTR 72

__global__ __launch_bounds__(128)
void attn_kernel(const float* __restrict__ qkv, float* __restrict__ out) {
    __shared__ float KPs[64 * KSTR];
    __shared__ float Vs [64 * VSTR];

    int bh = blockIdx.y;
    int b = bh >> 4, h = bh & 15;
    int q0 = blockIdx.x * 64;
    int tid = threadIdx.x;
    int w = tid >> 5, lane = tid & 31;
    int group = lane >> 2, tig = lane & 3;

    const size_t rs = 3 * D_MODEL;
    const float* qbase = qkv + (size_t)b * SEQ * rs + h * HEAD_DIM;
    const float* kbase = qbase + D_MODEL;
    const float* vbase = qbase + 2 * D_MODEL;

    // Q A-frags, pre-scaled by hd^-0.5 = 0.125, tf32 once.
    uint32_t aq[8][4];
    {
        int r0 = q0 + w * 16 + group, r1 = r0 + 8;
        #pragma unroll
        for (int kf = 0; kf < 8; kf++) {
            int d = kf * 8 + tig;
            aq[kf][0] = f2tf32(0.125f * qbase[(size_t)r0 * rs + d]);
            aq[kf][1] = f2tf32(0.125f * qbase[(size_t)r1 * rs + d]);
            aq[kf][2] = f2tf32(0.125f * qbase[(size_t)r0 * rs + d + 4]);
            aq[kf][3] = f2tf32(0.125f * qbase[(size_t)r1 * rs + d + 4]);
        }
    }

    float o[8][4] = {};
    float mrow[2] = {-1e30f, -1e30f};
    float lrow[2] = {0.0f, 0.0f};

    for (int k0 = 0; k0 < SEQ; k0 += 64) {
        __syncthreads();  // prior-iter consumers of KPs/Vs done
        // stage K, V (convert to tf32 at store). 64 rows x 16 float4 chunks.
        {
            int cr = tid >> 4, cc = (tid & 15) * 4;
            #pragma unroll
            for (int rep = 0; rep < 8; rep++) {
                int r = rep * 8 + cr;
                float4 kv = *reinterpret_cast<const float4*>(
                    kbase + (size_t)(k0 + r) * rs + cc);
                uint4 ku;
                ku.x = f2tf32(kv.x); ku.y = f2tf32(kv.y);
                ku.z = f2tf32(kv.z); ku.w = f2tf32(kv.w);
                *reinterpret_cast<uint4*>(&KPs[r * KSTR + cc]) = ku;
                float4 vv = *reinterpret_cast<const float4*>(
                    vbase + (size_t)(k0 + r) * rs + cc);
                uint4 vu;
                vu.x = f2tf32(vv.x); vu.y = f2tf32(vv.y);
                vu.z = f2tf32(vv.z); vu.w = f2tf32(vv.w);
                *reinterpret_cast<uint4*>(&Vs[r * VSTR + cc]) = vu;
            }
        }
        __syncthreads();

        // S = Q @ K^T  (m=q16, n=kseq, k=d)
        float s[8][4] = {};
        #pragma unroll
        for (int kf = 0; kf < 8; kf++) {
            #pragma unroll
            for (int nf = 0; nf < 8; nf++) {
                uint32_t bfr[2];
                const float* kp = &KPs[(nf * 8 + group) * KSTR + kf * 8 + tig];
                bfr[0] = __float_as_uint(kp[0]);
                bfr[1] = __float_as_uint(kp[4]);
                mma_tf32(s[nf], aq[kf], bfr);
            }
        }

        // online softmax; rows: r=0 -> group, r=1 -> group+8 (frag c idx 2r,2r+1)
        float al[2];
        #pragma unroll
        for (int r = 0; r < 2; r++) {
            float mx = -1e30f;
            #pragma unroll
            for (int nf = 0; nf < 8; nf++)
                mx = fmaxf(mx, fmaxf(s[nf][2 * r], s[nf][2 * r + 1]));
            mx = fmaxf(mx, __shfl_xor_sync(0xffffffffu, mx, 1));
            mx = fmaxf(mx, __shfl_xor_sync(0xffffffffu, mx, 2));
            float mn = fmaxf(mrow[r], mx);
            al[r] = __expf(mrow[r] - mn);
            float rsum = 0.0f;
            #pragma unroll
            for (int nf = 0; nf < 8; nf++) {
                float p0 = __expf(s[nf][2 * r]     - mn);
                float p1 = __expf(s[nf][2 * r + 1] - mn);
                s[nf][2 * r] = p0; s[nf][2 * r + 1] = p1;
                rsum += p0 + p1;
            }
            rsum += __shfl_xor_sync(0xffffffffu, rsum, 1);
            rsum += __shfl_xor_sync(0xffffffffu, rsum, 2);
            lrow[r] = lrow[r] * al[r] + rsum;
            mrow[r] = mn;
            #pragma unroll
            for (int nf = 0; nf < 8; nf++) {
                o[nf][2 * r]     *= al[r];
                o[nf][2 * r + 1] *= al[r];
            }
        }

        __syncthreads();  // all warps done reading KPs as K
        // store P (tf32) into KPs: rows w*16+group(+8), cols nf*8 + 2*tig
        {
            int pr0 = w * 16 + group;
            #pragma unroll
            for (int nf = 0; nf < 8; nf++) {
                int col = nf * 8 + 2 * tig;
                uint2 u0 = make_uint2(f2tf32(s[nf][0]), f2tf32(s[nf][1]));
                uint2 u1 = make_uint2(f2tf32(s[nf][2]), f2tf32(s[nf][3]));
                *reinterpret_cast<uint2*>(&KPs[pr0 * KSTR + col]) = u0;
                *reinterpret_cast<uint2*>(&KPs[(pr0 + 8) * KSTR + col]) = u1;
            }
        }
        __syncthreads();

        // O += P @ V  (m=q16, n=d, k=kseq)
        #pragma unroll
        for (int kf = 0; kf < 8; kf++) {
            uint32_t ap[4];
            const float* pp = &KPs[(w * 16 + group) * KSTR + kf * 8 + tig];
            ap[0] = __float_as_uint(pp[0]);
            ap[1] = __float_as_uint(pp[8 * KSTR]);
            ap[2] = __float_as_uint(pp[4]);
            ap[3] = __float_as_uint(pp[8 * KSTR + 4]);
            #pragma unroll
            for (int nf = 0; nf < 8; nf++) {
                uint32_t bfr[2];
                const float* vp = &Vs[(kf * 8 + tig) * VSTR + nf * 8 + group];
                bfr[0] = __float_as_uint(vp[0]);
                bfr[1] = __float_as_uint(vp[4 * VSTR]);
                mma_tf32(o[nf], ap, bfr);
            }
        }
    }

    // write O / l
    #pragma unroll
    for (int r = 0; r < 2; r++) {
        float inv = 1.0f / lrow[r];
        int row = q0 + w * 16 + group + 8 * r;
        float* orow = out + ((size_t)(b * SEQ + row)) * D_MODEL + h * HEAD_DIM;
        #pragma unroll
        for (int nf = 0; nf < 8; nf++) {
            int col = nf * 8 + 2 * tig;
            *reinterpret_cast<float2*>(orow + col) =
                make_float2(o[nf][2 * r] * inv, o[nf][2 * r + 1] * inv);
        }
    }
}

// ---------------------------------------------------------------- launch ----
extern "C" void kernel_launch(void* const* d_in, const int* in_sizes, int n_in,
                              void* d_out, int out_size) {
    const float* x     = (const float*)d_in[0];
    const float* n1    = (const float*)d_in[1];
    const float* wqkv  = (const float*)d_in[2];
    const float* wproj = (const float*)d_in[3];
    const float* n2    = (const float*)d_in[4];
    const float* wfc1  = (const float*)d_in[5];
    const float* wfc2  = (const float*)d_in[6];
    float* out = (float*)d_out;

    float *p_h, *p_qkv, *p_attn, *p_x1, *p_ffn;
    cudaGetSymbolAddress((void**)&p_h,    g_h);
    cudaGetSymbolAddress((void**)&p_qkv,  g_qkv);
    cudaGetSymbolAddress((void**)&p_attn, g_attn);
    cudaGetSymbolAddress((void**)&p_x1,   g_x1);
    cudaGetSymbolAddress((void**)&p_ffn,  g_ffn);

    dim3 blk(256);

    rmsnorm_kernel<<<M_TOK, blk>>>(x, n1, p_h);

    tgemm_kernel<0><<<dim3(3 * D_MODEL / BNT, M_TOK / BMT), blk>>>(
        p_h, wqkv, nullptr, p_qkv, M_TOK, 3 * D_MODEL, D_MODEL);

    attn_kernel<<<dim3(SEQ / 64, B_SZ * N_HEADS), dim3(128)>>>(p_qkv, p_attn);

    tgemm_kernel<1><<<dim3(D_MODEL / BNT, M_TOK / BMT), blk>>>(
        p_attn, wproj, x, p_x1, M_TOK, D_MODEL, D_MODEL);

    rmsnorm_kernel<<<M_TOK, blk>>>(p_x1, n2, p_h);

    tgemm_kernel<2><<<dim3(4 * D_MODEL / BNT, M_TOK / BMT), blk>>>(
        p_h, wfc1, nullptr, p_ffn, M_TOK, 4 * D_MODEL, D_MODEL);

    tgemm_kernel<1><<<dim3(D_MODEL / BNT, M_TOK / BMT), blk>>>(
        p_ffn, wfc2, p_x1, out, M_TOK, D_MODEL, 4 * D_MODEL);
}

// round 4
// speedup vs baseline: 5.6527x; 1.2007x over previous
#include <cuda_runtime.h>
#include <math.h>
#include <stdint.h>

#define D_MODEL 1024
#define N_HEADS 16
#define HEAD_DIM 64
#define B_SZ 4
#define SEQ 2048
#define M_TOK (B_SZ * SEQ)

// ---------------- scratch ----------------
__device__ float g_h   [(size_t)M_TOK * D_MODEL];
__device__ float g_qkv [(size_t)M_TOK * 3 * D_MODEL];
__device__ float g_attn[(size_t)M_TOK * D_MODEL];
__device__ float g_x1  [(size_t)M_TOK * D_MODEL];
__device__ float g_ffn [(size_t)M_TOK * 4 * D_MODEL];
// tf32-truncated weights
__device__ float g_wq [(size_t)D_MODEL * 3 * D_MODEL];
__device__ float g_wp [(size_t)D_MODEL * D_MODEL];
__device__ float g_w1 [(size_t)D_MODEL * 4 * D_MODEL];
__device__ float g_w2 [(size_t)4 * D_MODEL * D_MODEL];

// ------------------------------------------------------- common tf32 bits ---
__device__ __forceinline__ uint32_t f2tf32(float x) {
    uint32_t r;
    asm("cvt.rna.tf32.f32 %0, %1;" : "=r"(r) : "f"(x));
    return r;
}
__device__ __forceinline__ void mma_tf32(float* c, const uint32_t* a, const uint32_t* b) {
    asm volatile(
        "mma.sync.aligned.m16n8k8.row.col.f32.tf32.tf32.f32 "
        "{%0,%1,%2,%3}, {%4,%5,%6,%7}, {%8,%9}, {%0,%1,%2,%3};"
        : "+f"(c[0]), "+f"(c[1]), "+f"(c[2]), "+f"(c[3])
        : "r"(a[0]), "r"(a[1]), "r"(a[2]), "r"(a[3]), "r"(b[0]), "r"(b[1]));
}
__device__ __forceinline__ void cp_async16(uint32_t smem, const void* gmem) {
    asm volatile("cp.async.cg.shared.global [%0], [%1], 16;\n" ::"r"(smem), "l"(gmem));
}
__device__ __forceinline__ float gelu_exact(float v) {
    return 0.5f * v * (1.0f + erff(v * 0.70710678118654752f));
}

// -------------------------------------------------- tf32 truncation pass ---
__global__ void tf32_trunc_kernel(const float* __restrict__ in,
                                  float* __restrict__ out, int n4) {
    int i = blockIdx.x * blockDim.x + threadIdx.x;
    if (i >= n4) return;
    float4 v = reinterpret_cast<const float4*>(in)[i];
    uint4 u;
    u.x = f2tf32(v.x); u.y = f2tf32(v.y); u.z = f2tf32(v.z); u.w = f2tf32(v.w);
    reinterpret_cast<uint4*>(out)[i] = u;
}

// ------------------------------------------- RMSNorm (tf32-trunc output) ---
__global__ void rmsnorm_kernel(const float* __restrict__ x,
                               const float* __restrict__ scale,
                               float* __restrict__ out) {
    int row = blockIdx.x;
    int t = threadIdx.x;
    const float4* xr = reinterpret_cast<const float4*>(x + (size_t)row * D_MODEL);
    float4 v = xr[t];
    float ss = v.x * v.x + v.y * v.y + v.z * v.z + v.w * v.w;
    #pragma unroll
    for (int o = 16; o > 0; o >>= 1) ss += __shfl_xor_sync(0xffffffffu, ss, o);
    __shared__ float wsum[8];
    if ((t & 31) == 0) wsum[t >> 5] = ss;
    __syncthreads();
    if (t < 8) {
        float s2 = wsum[t];
        #pragma unroll
        for (int o = 4; o > 0; o >>= 1) s2 += __shfl_xor_sync(0xffu, s2, o);
        if (t == 0) wsum[0] = s2;
    }
    __syncthreads();
    float inv = rsqrtf(wsum[0] * (1.0f / D_MODEL) + 1e-8f);
    float4 s4 = reinterpret_cast<const float4*>(scale)[t];
    uint4 o4;
    o4.x = f2tf32(v.x * inv * s4.x);
    o4.y = f2tf32(v.y * inv * s4.y);
    o4.z = f2tf32(v.z * inv * s4.z);
    o4.w = f2tf32(v.w * inv * s4.w);
    reinterpret_cast<uint4*>(out + (size_t)row * D_MODEL)[t] = o4;
}

// ------------------------------------------------------- TF32 tensor GEMM ---
// Inputs A,B must already be tf32-truncated. Inner loop: pure LDS + MMA.
#define BMT 128
#define BNT 128
#define BKT 16
#define ASTR 20
#define BSTR 136

template <int EPI, int TRUNC>  // EPI: 0 none, 1 +residual, 2 gelu
__global__ __launch_bounds__(256)
void tgemm_kernel(const float* __restrict__ A, const float* __restrict__ Bm,
                  const float* __restrict__ R, float* __restrict__ C,
                  int M, int N, int K) {
    __shared__ float As[2][BMT * ASTR];
    __shared__ float Bs[2][BKT * BSTR];

    int tid = threadIdx.x;
    int warp = tid >> 5, lane = tid & 31;
    int group = lane >> 2, tig = lane & 3;
    int wm = warp >> 2, wn = warp & 3;
    int bm = blockIdx.y * BMT, bn = blockIdx.x * BNT;

    uint32_t sA[2], sB[2];
    sA[0] = (uint32_t)__cvta_generic_to_shared(&As[0][0]);
    sA[1] = (uint32_t)__cvta_generic_to_shared(&As[1][0]);
    sB[0] = (uint32_t)__cvta_generic_to_shared(&Bs[0][0]);
    sB[1] = (uint32_t)__cvta_generic_to_shared(&Bs[1][0]);

    int a_row0 = tid >> 2, a_c0 = (tid & 3) * 4;
    int a_row1 = (tid + 256) >> 2, a_c1 = ((tid + 256) & 3) * 4;
    int b_row0 = tid >> 5, b_c0 = (tid & 31) * 4;
    int b_row1 = (tid + 256) >> 5, b_c1 = ((tid + 256) & 31) * 4;

    auto load_stage = [&](int s, int k0) {
        cp_async16(sA[s] + (uint32_t)(a_row0 * ASTR + a_c0) * 4,
                   A + (size_t)(bm + a_row0) * K + k0 + a_c0);
        cp_async16(sA[s] + (uint32_t)(a_row1 * ASTR + a_c1) * 4,
                   A + (size_t)(bm + a_row1) * K + k0 + a_c1);
        cp_async16(sB[s] + (uint32_t)(b_row0 * BSTR + b_c0) * 4,
                   Bm + (size_t)(k0 + b_row0) * N + bn + b_c0);
        cp_async16(sB[s] + (uint32_t)(b_row1 * BSTR + b_c1) * 4,
                   Bm + (size_t)(k0 + b_row1) * N + bn + b_c1);
        asm volatile("cp.async.commit_group;\n" ::);
    };

    float c[4][4][4] = {};
    int KT = K / BKT;
    load_stage(0, 0);

    for (int kt = 0; kt < KT; kt++) {
        asm volatile("cp.async.wait_group 0;\n" ::);
        __syncthreads();
        if (kt + 1 < KT) load_stage((kt + 1) & 1, (kt + 1) * BKT);
        int s = kt & 1;

        #pragma unroll
        for (int ks = 0; ks < BKT; ks += 8) {
            uint32_t af[4][4], bf[4][2];
            #pragma unroll
            for (int mt = 0; mt < 4; mt++) {
                int m = wm * 64 + mt * 16 + group;
                const float* base = &As[s][0];
                af[mt][0] = __float_as_uint(base[(m)     * ASTR + ks + tig]);
                af[mt][1] = __float_as_uint(base[(m + 8) * ASTR + ks + tig]);
                af[mt][2] = __float_as_uint(base[(m)     * ASTR + ks + tig + 4]);
                af[mt][3] = __float_as_uint(base[(m + 8) * ASTR + ks + tig + 4]);
            }
            #pragma unroll
            for (int nt = 0; nt < 4; nt++) {
                int n = wn * 32 + nt * 8 + group;
                const float* base = &Bs[s][0];
                bf[nt][0] = __float_as_uint(base[(ks + tig)     * BSTR + n]);
                bf[nt][1] = __float_as_uint(base[(ks + tig + 4) * BSTR + n]);
            }
            #pragma unroll
            for (int mt = 0; mt < 4; mt++)
                #pragma unroll
                for (int nt = 0; nt < 4; nt++)
                    mma_tf32(c[mt][nt], af[mt], bf[nt]);
        }
        __syncthreads();
    }

    #pragma unroll
    for (int mt = 0; mt < 4; mt++) {
        #pragma unroll
        for (int half = 0; half < 2; half++) {
            int row = bm + wm * 64 + mt * 16 + group + half * 8;
            float* Crow = C + (size_t)row * N;
            const float* Rrow = (EPI == 1) ? (R + (size_t)row * N) : nullptr;
            #pragma unroll
            for (int nt = 0; nt < 4; nt++) {
                int col = bn + wn * 32 + nt * 8 + tig * 2;
                float v0 = c[mt][nt][half * 2 + 0];
                float v1 = c[mt][nt][half * 2 + 1];
                if (EPI == 2) { v0 = gelu_exact(v0); v1 = gelu_exact(v1); }
                if (EPI == 1) {
                    float2 r2 = *reinterpret_cast<const float2*>(Rrow + col);
                    v0 += r2.x; v1 += r2.y;
                }
                if (TRUNC) {
                    v0 = __uint_as_float(f2tf32(v0));
                    v1 = __uint_as_float(f2tf32(v1));
                }
                *reinterpret_cast<float2*>(Crow + col) = make_float2(v0, v1);
            }
        }
    }
}

// ----------------------------------------- TF32 tensor flash attention -----
// qkv is pre-truncated tf32; only P needs cvt. Output stored tf32-truncated.
#define KSTR 68
#define VSTR 72

__global__ __launch_bounds__(128)
void attn_kernel(const float* __restrict__ qkv, float* __restrict__ out) {
    __shared__ float KPs[64 * KSTR];
    __shared__ float Vs [64 * VSTR];

    int bh = blockIdx.y;
    int b = bh >> 4, h = bh & 15;
    int q0 = blockIdx.x * 64;
    int tid = threadIdx.x;
    int w = tid >> 5, lane = tid & 31;
    int group = lane >> 2, tig = lane & 3;

    const size_t rs = 3 * D_MODEL;
    const float* qbase = qkv + (size_t)b * SEQ * rs + h * HEAD_DIM;
    const float* kbase = qbase + D_MODEL;
    const float* vbase = qbase + 2 * D_MODEL;

    // Q A-frags: scale by 0.125 (power of two -> stays tf32-exact)
    uint32_t aq[8][4];
    {
        int r0 = q0 + w * 16 + group, r1 = r0 + 8;
        #pragma unroll
        for (int kf = 0; kf < 8; kf++) {
            int d = kf * 8 + tig;
            aq[kf][0] = __float_as_uint(0.125f * qbase[(size_t)r0 * rs + d]);
            aq[kf][1] = __float_as_uint(0.125f * qbase[(size_t)r1 * rs + d]);
            aq[kf][2] = __float_as_uint(0.125f * qbase[(size_t)r0 * rs + d + 4]);
            aq[kf][3] = __float_as_uint(0.125f * qbase[(size_t)r1 * rs + d + 4]);
        }
    }

    float o[8][4] = {};
    float mrow[2] = {-1e30f, -1e30f};
    float lrow[2] = {0.0f, 0.0f};

    for (int k0 = 0; k0 < SEQ; k0 += 64) {
        __syncthreads();
        {
            int cr = tid >> 4, cc = (tid & 15) * 4;
            #pragma unroll
            for (int rep = 0; rep < 8; rep++) {
                int r = rep * 8 + cr;
                float4 kv = *reinterpret_cast<const float4*>(
                    kbase + (size_t)(k0 + r) * rs + cc);
                *reinterpret_cast<float4*>(&KPs[r * KSTR + cc]) = kv;
                float4 vv = *reinterpret_cast<const float4*>(
                    vbase + (size_t)(k0 + r) * rs + cc);
                *reinterpret_cast<float4*>(&Vs[r * VSTR + cc]) = vv;
            }
        }
        __syncthreads();

        // S = Q @ K^T
        float s[8][4] = {};
        #pragma unroll
        for (int kf = 0; kf < 8; kf++) {
            #pragma unroll
            for (int nf = 0; nf < 8; nf++) {
                uint32_t bfr[2];
                const float* kp = &KPs[(nf * 8 + group) * KSTR + kf * 8 + tig];
                bfr[0] = __float_as_uint(kp[0]);
                bfr[1] = __float_as_uint(kp[4]);
                mma_tf32(s[nf], aq[kf], bfr);
            }
        }

        // online softmax
        float al[2];
        #pragma unroll
        for (int r = 0; r < 2; r++) {
            float mx = -1e30f;
            #pragma unroll
            for (int nf = 0; nf < 8; nf++)
                mx = fmaxf(mx, fmaxf(s[nf][2 * r], s[nf][2 * r + 1]));
            mx = fmaxf(mx, __shfl_xor_sync(0xffffffffu, mx, 1));
            mx = fmaxf(mx, __shfl_xor_sync(0xffffffffu, mx, 2));
            float mn = fmaxf(mrow[r], mx);
            al[r] = __expf(mrow[r] - mn);
            float rsum = 0.0f;
            #pragma unroll
            for (int nf = 0; nf < 8; nf++) {
                float p0 = __expf(s[nf][2 * r]     - mn);
                float p1 = __expf(s[nf][2 * r + 1] - mn);
                s[nf][2 * r] = p0; s[nf][2 * r + 1] = p1;
                rsum += p0 + p1;
            }
            rsum += __shfl_xor_sync(0xffffffffu, rsum, 1);
            rsum += __shfl_xor_sync(0xffffffffu, rsum, 2);
            lrow[r] = lrow[r] * al[r] + rsum;
            mrow[r] = mn;
            #pragma unroll
            for (int nf = 0; nf < 8; nf++) {
                o[nf][2 * r]     *= al[r];
                o[nf][2 * r + 1] *= al[r];
            }
        }

        __syncthreads();
        {
            int pr0 = w * 16 + group;
            #pragma unroll
            for (int nf = 0; nf < 8; nf++) {
                int col = nf * 8 + 2 * tig;
                uint2 u0 = make_uint2(f2tf32(s[nf][0]), f2tf32(s[nf][1]));
                uint2 u1 = make_uint2(f2tf32(s[nf][2]), f2tf32(s[nf][3]));
                *reinterpret_cast<uint2*>(&KPs[pr0 * KSTR + col]) = u0;
                *reinterpret_cast<uint2*>(&KPs[(pr0 + 8) * KSTR + col]) = u1;
            }
        }
        __syncthreads();

        // O += P @ V
        #pragma unroll
        for (int kf = 0; kf < 8; kf++) {
            uint32_t ap[4];
            const float* pp = &KPs[(w * 16 + group) * KSTR + kf * 8 + tig];
            ap[0] = __float_as_uint(pp[0]);
            ap[1] = __float_as_uint(pp[8 * KSTR]);
            ap[2] = __float_as_uint(pp[4]);
            ap[3] = __float_as_uint(pp[8 * KSTR + 4]);
            #pragma unroll
            for (int nf = 0; nf < 8; nf++) {
                uint32_t bfr[2];
                const float* vp = &Vs[(kf * 8 + tig) * VSTR + nf * 8 + group];
                bfr[0] = __float_as_uint(vp[0]);
                bfr[1] = __float_as_uint(vp[4 * VSTR]);
                mma_tf32(o[nf], ap, bfr);
            }
        }
    }

    #pragma unroll
    for (int r = 0; r < 2; r++) {
        float inv = 1.0f / lrow[r];
        int row = q0 + w * 16 + group + 8 * r;
        float* orow = out + ((size_t)(b * SEQ + row)) * D_MODEL + h * HEAD_DIM;
        #pragma unroll
        for (int nf = 0; nf < 8; nf++) {
            int col = nf * 8 + 2 * tig;
            uint2 u = make_uint2(f2tf32(o[nf][2 * r] * inv),
                                 f2tf32(o[nf][2 * r + 1] * inv));
            *reinterpret_cast<uint2*>(orow + col) = u;
        }
    }
}

// ---------------------------------------------------------------- launch ----
extern "C" void kernel_launch(void* const* d_in, const int* in_sizes, int n_in,
                              void* d_out, int out_size) {
    const float* x     = (const float*)d_in[0];
    const float* n1    = (const float*)d_in[1];
    const float* wqkv  = (const float*)d_in[2];
    const float* wproj = (const float*)d_in[3];
    const float* n2    = (const float*)d_in[4];
    const float* wfc1  = (const float*)d_in[5];
    const float* wfc2  = (const float*)d_in[6];
    float* out = (float*)d_out;

    float *p_h, *p_qkv, *p_attn, *p_x1, *p_ffn;
    float *p_wq, *p_wp, *p_w1, *p_w2;
    cudaGetSymbolAddress((void**)&p_h,    g_h);
    cudaGetSymbolAddress((void**)&p_qkv,  g_qkv);
    cudaGetSymbolAddress((void**)&p_attn, g_attn);
    cudaGetSymbolAddress((void**)&p_x1,   g_x1);
    cudaGetSymbolAddress((void**)&p_ffn,  g_ffn);
    cudaGetSymbolAddress((void**)&p_wq,   g_wq);
    cudaGetSymbolAddress((void**)&p_wp,   g_wp);
    cudaGetSymbolAddress((void**)&p_w1,   g_w1);
    cudaGetSymbolAddress((void**)&p_w2,   g_w2);

    dim3 blk(256);

    // weight truncation passes (tf32-ready weights)
    {
        int n4;
        n4 = (D_MODEL * 3 * D_MODEL) / 4;
        tf32_trunc_kernel<<<(n4 + 255) / 256, blk>>>(wqkv, p_wq, n4);
        n4 = (D_MODEL * D_MODEL) / 4;
        tf32_trunc_kernel<<<(n4 + 255) / 256, blk>>>(wproj, p_wp, n4);
        n4 = (D_MODEL * 4 * D_MODEL) / 4;
        tf32_trunc_kernel<<<(n4 + 255) / 256, blk>>>(wfc1, p_w1, n4);
        n4 = (4 * D_MODEL * D_MODEL) / 4;
        tf32_trunc_kernel<<<(n4 + 255) / 256, blk>>>(wfc2, p_w2, n4);
    }

    rmsnorm_kernel<<<M_TOK, blk>>>(x, n1, p_h);

    tgemm_kernel<0, 1><<<dim3(3 * D_MODEL / BNT, M_TOK / BMT), blk>>>(
        p_h, p_wq, nullptr, p_qkv, M_TOK, 3 * D_MODEL, D_MODEL);

    attn_kernel<<<dim3(SEQ / 64, B_SZ * N_HEADS), dim3(128)>>>(p_qkv, p_attn);

    tgemm_kernel<1, 0><<<dim3(D_MODEL / BNT, M_TOK / BMT), blk>>>(
        p_attn, p_wp, x, p_x1, M_TOK, D_MODEL, D_MODEL);

    rmsnorm_kernel<<<M_TOK, blk>>>(p_x1, n2, p_h);

    tgemm_kernel<2, 1><<<dim3(4 * D_MODEL / BNT, M_TOK / BMT), blk>>>(
        p_h, p_w1, nullptr, p_ffn, M_TOK, 4 * D_MODEL, D_MODEL);

    tgemm_kernel<1, 0><<<dim3(D_MODEL / BNT, M_TOK / BMT), blk>>>(
        p_ffn, p_w2, p_x1, out, M_TOK, D_MODEL, 4 * D_MODEL);
}

// round 5
// speedup vs baseline: 6.2984x; 1.1142x over previous
#include <cuda_runtime.h>
#include <math.h>
#include <stdint.h>

#define D_MODEL 1024
#define N_HEADS 16
#define HEAD_DIM 64
#define B_SZ 4
#define SEQ 2048
#define M_TOK (B_SZ * SEQ)

// ---------------- scratch ----------------
__device__ float g_h   [(size_t)M_TOK * D_MODEL];
__device__ float g_qkv [(size_t)M_TOK * 3 * D_MODEL];
__device__ float g_attn[(size_t)M_TOK * D_MODEL];
__device__ float g_x1  [(size_t)M_TOK * D_MODEL];
__device__ float g_ffn [(size_t)M_TOK * 4 * D_MODEL];
// tf32-truncated weights
__device__ float g_wq [(size_t)D_MODEL * 3 * D_MODEL];
__device__ float g_wp [(size_t)D_MODEL * D_MODEL];
__device__ float g_w1 [(size_t)D_MODEL * 4 * D_MODEL];
__device__ float g_w2 [(size_t)4 * D_MODEL * D_MODEL];

// ------------------------------------------------------- common tf32 bits ---
__device__ __forceinline__ uint32_t f2tf32(float x) {
    uint32_t r;
    asm("cvt.rna.tf32.f32 %0, %1;" : "=r"(r) : "f"(x));
    return r;
}
__device__ __forceinline__ void mma_tf32(float* c, const uint32_t* a, const uint32_t* b) {
    asm volatile(
        "mma.sync.aligned.m16n8k8.row.col.f32.tf32.tf32.f32 "
        "{%0,%1,%2,%3}, {%4,%5,%6,%7}, {%8,%9}, {%0,%1,%2,%3};"
        : "+f"(c[0]), "+f"(c[1]), "+f"(c[2]), "+f"(c[3])
        : "r"(a[0]), "r"(a[1]), "r"(a[2]), "r"(a[3]), "r"(b[0]), "r"(b[1]));
}
__device__ __forceinline__ void cp_async16(uint32_t smem, const void* gmem) {
    asm volatile("cp.async.cg.shared.global [%0], [%1], 16;\n" ::"r"(smem), "l"(gmem));
}
__device__ __forceinline__ float gelu_exact(float v) {
    return 0.5f * v * (1.0f + erff(v * 0.70710678118654752f));
}

// -------------------------------------------------- tf32 truncation pass ---
__global__ void tf32_trunc_kernel(const float* __restrict__ in,
                                  float* __restrict__ out, int n4) {
    int i = blockIdx.x * blockDim.x + threadIdx.x;
    if (i >= n4) return;
    float4 v = reinterpret_cast<const float4*>(in)[i];
    uint4 u;
    u.x = f2tf32(v.x); u.y = f2tf32(v.y); u.z = f2tf32(v.z); u.w = f2tf32(v.w);
    reinterpret_cast<uint4*>(out)[i] = u;
}

// ------------------------------------------- RMSNorm (tf32-trunc output) ---
__global__ void rmsnorm_kernel(const float* __restrict__ x,
                               const float* __restrict__ scale,
                               float* __restrict__ out) {
    int row = blockIdx.x;
    int t = threadIdx.x;
    const float4* xr = reinterpret_cast<const float4*>(x + (size_t)row * D_MODEL);
    float4 v = xr[t];
    float ss = v.x * v.x + v.y * v.y + v.z * v.z + v.w * v.w;
    #pragma unroll
    for (int o = 16; o > 0; o >>= 1) ss += __shfl_xor_sync(0xffffffffu, ss, o);
    __shared__ float wsum[8];
    if ((t & 31) == 0) wsum[t >> 5] = ss;
    __syncthreads();
    if (t < 8) {
        float s2 = wsum[t];
        #pragma unroll
        for (int o = 4; o > 0; o >>= 1) s2 += __shfl_xor_sync(0xffu, s2, o);
        if (t == 0) wsum[0] = s2;
    }
    __syncthreads();
    float inv = rsqrtf(wsum[0] * (1.0f / D_MODEL) + 1e-8f);
    float4 s4 = reinterpret_cast<const float4*>(scale)[t];
    uint4 o4;
    o4.x = f2tf32(v.x * inv * s4.x);
    o4.y = f2tf32(v.y * inv * s4.y);
    o4.z = f2tf32(v.z * inv * s4.z);
    o4.w = f2tf32(v.w * inv * s4.w);
    reinterpret_cast<uint4*>(out + (size_t)row * D_MODEL)[t] = o4;
}

// ------------------------------------------------------- TF32 tensor GEMM ---
// 3-stage cp.async ring, ONE __syncthreads per k-tile.
#define BMT 128
#define BNT 128
#define BKT 16
#define ASTR 20
#define BSTR 136
#define A_STG (BMT * ASTR)   // floats per A stage
#define B_STG (BKT * BSTR)   // floats per B stage
#define GEMM_SMEM ((3 * (A_STG + B_STG)) * 4)

template <int EPI, int TRUNC>  // EPI: 0 none, 1 +residual, 2 gelu
__global__ __launch_bounds__(256, 2)
void tgemm_kernel(const float* __restrict__ A, const float* __restrict__ Bm,
                  const float* __restrict__ R, float* __restrict__ C,
                  int M, int N, int K) {
    extern __shared__ float dsm[];
    float* Asm = dsm;                 // 3 * A_STG
    float* Bsm = dsm + 3 * A_STG;     // 3 * B_STG

    int tid = threadIdx.x;
    int warp = tid >> 5, lane = tid & 31;
    int group = lane >> 2, tig = lane & 3;
    int wm = warp >> 2, wn = warp & 3;
    int bm = blockIdx.y * BMT, bn = blockIdx.x * BNT;

    uint32_t sA = (uint32_t)__cvta_generic_to_shared(Asm);
    uint32_t sB = (uint32_t)__cvta_generic_to_shared(Bsm);

    int a_row0 = tid >> 2, a_c0 = (tid & 3) * 4;
    int a_row1 = (tid + 256) >> 2, a_c1 = ((tid + 256) & 3) * 4;
    int b_row0 = tid >> 5, b_c0 = (tid & 31) * 4;
    int b_row1 = (tid + 256) >> 5, b_c1 = ((tid + 256) & 31) * 4;

    auto load_stage = [&](int s, int k0) {
        uint32_t aS = sA + (uint32_t)(s * A_STG) * 4;
        uint32_t bS = sB + (uint32_t)(s * B_STG) * 4;
        cp_async16(aS + (uint32_t)(a_row0 * ASTR + a_c0) * 4,
                   A + (size_t)(bm + a_row0) * K + k0 + a_c0);
        cp_async16(aS + (uint32_t)(a_row1 * ASTR + a_c1) * 4,
                   A + (size_t)(bm + a_row1) * K + k0 + a_c1);
        cp_async16(bS + (uint32_t)(b_row0 * BSTR + b_c0) * 4,
                   Bm + (size_t)(k0 + b_row0) * N + bn + b_c0);
        cp_async16(bS + (uint32_t)(b_row1 * BSTR + b_c1) * 4,
                   Bm + (size_t)(k0 + b_row1) * N + bn + b_c1);
    };

    float c[4][4][4] = {};
    int KT = K / BKT;

    load_stage(0, 0);
    asm volatile("cp.async.commit_group;\n" ::);
    load_stage(1, BKT);
    asm volatile("cp.async.commit_group;\n" ::);

    int s = 0, sn = 2;
    for (int kt = 0; kt < KT; kt++) {
        asm volatile("cp.async.wait_group 1;\n" ::);
        __syncthreads();
        if (kt + 2 < KT) load_stage(sn, (kt + 2) * BKT);
        asm volatile("cp.async.commit_group;\n" ::);

        const float* As = Asm + s * A_STG;
        const float* Bs = Bsm + s * B_STG;

        #pragma unroll
        for (int ks = 0; ks < BKT; ks += 8) {
            uint32_t af[4][4], bf[4][2];
            #pragma unroll
            for (int mt = 0; mt < 4; mt++) {
                int m = wm * 64 + mt * 16 + group;
                af[mt][0] = __float_as_uint(As[(m)     * ASTR + ks + tig]);
                af[mt][1] = __float_as_uint(As[(m + 8) * ASTR + ks + tig]);
                af[mt][2] = __float_as_uint(As[(m)     * ASTR + ks + tig + 4]);
                af[mt][3] = __float_as_uint(As[(m + 8) * ASTR + ks + tig + 4]);
            }
            #pragma unroll
            for (int nt = 0; nt < 4; nt++) {
                int n = wn * 32 + nt * 8 + group;
                bf[nt][0] = __float_as_uint(Bs[(ks + tig)     * BSTR + n]);
                bf[nt][1] = __float_as_uint(Bs[(ks + tig + 4) * BSTR + n]);
            }
            #pragma unroll
            for (int mt = 0; mt < 4; mt++)
                #pragma unroll
                for (int nt = 0; nt < 4; nt++)
                    mma_tf32(c[mt][nt], af[mt], bf[nt]);
        }
        s  = (s  == 2) ? 0 : s + 1;
        sn = (sn == 2) ? 0 : sn + 1;
    }

    #pragma unroll
    for (int mt = 0; mt < 4; mt++) {
        #pragma unroll
        for (int half = 0; half < 2; half++) {
            int row = bm + wm * 64 + mt * 16 + group + half * 8;
            float* Crow = C + (size_t)row * N;
            const float* Rrow = (EPI == 1) ? (R + (size_t)row * N) : nullptr;
            #pragma unroll
            for (int nt = 0; nt < 4; nt++) {
                int col = bn + wn * 32 + nt * 8 + tig * 2;
                float v0 = c[mt][nt][half * 2 + 0];
                float v1 = c[mt][nt][half * 2 + 1];
                if (EPI == 2) { v0 = gelu_exact(v0); v1 = gelu_exact(v1); }
                if (EPI == 1) {
                    float2 r2 = *reinterpret_cast<const float2*>(Rrow + col);
                    v0 += r2.x; v1 += r2.y;
                }
                if (TRUNC) {
                    v0 = __uint_as_float(f2tf32(v0));
                    v1 = __uint_as_float(f2tf32(v1));
                }
                *reinterpret_cast<float2*>(Crow + col) = make_float2(v0, v1);
            }
        }
    }
}

// ----------------------------------------- TF32 tensor flash attention -----
// 2-stage cp.async K/V double buffer; prefetch overlaps S+softmax+P@V.
// P overwrites the CURRENT K stage. qkv pre-truncated tf32.
#define KSTR 68
#define VSTR 72
#define K_STG (64 * KSTR)
#define V_STG (64 * VSTR)
#define ATTN_SMEM ((2 * (K_STG + V_STG)) * 4)

__global__ __launch_bounds__(128)
void attn_kernel(const float* __restrict__ qkv, float* __restrict__ out) {
    extern __shared__ float dsm[];
    float* Kst = dsm;                 // 2 * K_STG
    float* Vst = dsm + 2 * K_STG;     // 2 * V_STG

    int bh = blockIdx.y;
    int b = bh >> 4, h = bh & 15;
    int q0 = blockIdx.x * 64;
    int tid = threadIdx.x;
    int w = tid >> 5, lane = tid & 31;
    int group = lane >> 2, tig = lane & 3;

    const size_t rs = 3 * D_MODEL;
    const float* qbase = qkv + (size_t)b * SEQ * rs + h * HEAD_DIM;
    const float* kbase = qbase + D_MODEL;
    const float* vbase = qbase + 2 * D_MODEL;

    uint32_t sK = (uint32_t)__cvta_generic_to_shared(Kst);
    uint32_t sV = (uint32_t)__cvta_generic_to_shared(Vst);
    int cr = tid >> 4, cc = (tid & 15) * 4;

    auto stage_kv = [&](int st, int k0) {
        uint32_t kS = sK + (uint32_t)(st * K_STG) * 4;
        uint32_t vS = sV + (uint32_t)(st * V_STG) * 4;
        #pragma unroll
        for (int rep = 0; rep < 8; rep++) {
            int r = rep * 8 + cr;
            cp_async16(kS + (uint32_t)(r * KSTR + cc) * 4,
                       kbase + (size_t)(k0 + r) * rs + cc);
            cp_async16(vS + (uint32_t)(r * VSTR + cc) * 4,
                       vbase + (size_t)(k0 + r) * rs + cc);
        }
        asm volatile("cp.async.commit_group;\n" ::);
    };

    // Q A-frags, scaled by 0.125 (exponent-only -> stays tf32-exact)
    uint32_t aq[8][4];
    {
        int r0 = q0 + w * 16 + group, r1 = r0 + 8;
        #pragma unroll
        for (int kf = 0; kf < 8; kf++) {
            int d = kf * 8 + tig;
            aq[kf][0] = __float_as_uint(0.125f * qbase[(size_t)r0 * rs + d]);
            aq[kf][1] = __float_as_uint(0.125f * qbase[(size_t)r1 * rs + d]);
            aq[kf][2] = __float_as_uint(0.125f * qbase[(size_t)r0 * rs + d + 4]);
            aq[kf][3] = __float_as_uint(0.125f * qbase[(size_t)r1 * rs + d + 4]);
        }
    }

    float o[8][4] = {};
    float mrow[2] = {-1e30f, -1e30f};
    float lrow[2] = {0.0f, 0.0f};

    stage_kv(0, 0);
    int cur = 0;

    for (int k0 = 0; k0 < SEQ; k0 += 64) {
        asm volatile("cp.async.wait_group 0;\n" ::);
        __syncthreads();                       // stage `cur` ready, warps aligned
        if (k0 + 64 < SEQ) stage_kv(cur ^ 1, k0 + 64);  // overlap with compute

        float* Kc = Kst + cur * K_STG;
        float* Vc = Vst + cur * V_STG;

        // S = Q @ K^T
        float s[8][4] = {};
        #pragma unroll
        for (int kf = 0; kf < 8; kf++) {
            #pragma unroll
            for (int nf = 0; nf < 8; nf++) {
                uint32_t bfr[2];
                const float* kp = &Kc[(nf * 8 + group) * KSTR + kf * 8 + tig];
                bfr[0] = __float_as_uint(kp[0]);
                bfr[1] = __float_as_uint(kp[4]);
                mma_tf32(s[nf], aq[kf], bfr);
            }
        }

        // online softmax
        float al[2];
        #pragma unroll
        for (int r = 0; r < 2; r++) {
            float mx = -1e30f;
            #pragma unroll
            for (int nf = 0; nf < 8; nf++)
                mx = fmaxf(mx, fmaxf(s[nf][2 * r], s[nf][2 * r + 1]));
            mx = fmaxf(mx, __shfl_xor_sync(0xffffffffu, mx, 1));
            mx = fmaxf(mx, __shfl_xor_sync(0xffffffffu, mx, 2));
            float mn = fmaxf(mrow[r], mx);
            al[r] = __expf(mrow[r] - mn);
            float rsum = 0.0f;
            #pragma unroll
            for (int nf = 0; nf < 8; nf++) {
                float p0 = __expf(s[nf][2 * r]     - mn);
                float p1 = __expf(s[nf][2 * r + 1] - mn);
                s[nf][2 * r] = p0; s[nf][2 * r + 1] = p1;
                rsum += p0 + p1;
            }
            rsum += __shfl_xor_sync(0xffffffffu, rsum, 1);
            rsum += __shfl_xor_sync(0xffffffffu, rsum, 2);
            lrow[r] = lrow[r] * al[r] + rsum;
            mrow[r] = mn;
            #pragma unroll
            for (int nf = 0; nf < 8; nf++) {
                o[nf][2 * r]     *= al[r];
                o[nf][2 * r + 1] *= al[r];
            }
        }

        __syncthreads();                       // all warps done reading K
        {
            int pr0 = w * 16 + group;
            #pragma unroll
            for (int nf = 0; nf < 8; nf++) {
                int col = nf * 8 + 2 * tig;
                uint2 u0 = make_uint2(f2tf32(s[nf][0]), f2tf32(s[nf][1]));
                uint2 u1 = make_uint2(f2tf32(s[nf][2]), f2tf32(s[nf][3]));
                *reinterpret_cast<uint2*>(&Kc[pr0 * KSTR + col]) = u0;
                *reinterpret_cast<uint2*>(&Kc[(pr0 + 8) * KSTR + col]) = u1;
            }
        }
        __syncthreads();

        // O += P @ V
        #pragma unroll
        for (int kf = 0; kf < 8; kf++) {
            uint32_t ap[4];
            const float* pp = &Kc[(w * 16 + group) * KSTR + kf * 8 + tig];
            ap[0] = __float_as_uint(pp[0]);
            ap[1] = __float_as_uint(pp[8 * KSTR]);
            ap[2] = __float_as_uint(pp[4]);
            ap[3] = __float_as_uint(pp[8 * KSTR + 4]);
            #pragma unroll
            for (int nf = 0; nf < 8; nf++) {
                uint32_t bfr[2];
                const float* vp = &Vc[(kf * 8 + tig) * VSTR + nf * 8 + group];
                bfr[0] = __float_as_uint(vp[0]);
                bfr[1] = __float_as_uint(vp[4 * VSTR]);
                mma_tf32(o[nf], ap, bfr);
            }
        }
        cur ^= 1;
    }

    #pragma unroll
    for (int r = 0; r < 2; r++) {
        float inv = 1.0f / lrow[r];
        int row = q0 + w * 16 + group + 8 * r;
        float* orow = out + ((size_t)(b * SEQ + row)) * D_MODEL + h * HEAD_DIM;
        #pragma unroll
        for (int nf = 0; nf < 8; nf++) {
            int col = nf * 8 + 2 * tig;
            uint2 u = make_uint2(f2tf32(o[nf][2 * r] * inv),
                                 f2tf32(o[nf][2 * r + 1] * inv));
            *reinterpret_cast<uint2*>(orow + col) = u;
        }
    }
}

// ---------------------------------------------------------------- launch ----
extern "C" void kernel_launch(void* const* d_in, const int* in_sizes, int n_in,
                              void* d_out, int out_size) {
    const float* x     = (const float*)d_in[0];
    const float* n1    = (const float*)d_in[1];
    const float* wqkv  = (const float*)d_in[2];
    const float* wproj = (const float*)d_in[3];
    const float* n2    = (const float*)d_in[4];
    const float* wfc1  = (const float*)d_in[5];
    const float* wfc2  = (const float*)d_in[6];
    float* out = (float*)d_out;

    float *p_h, *p_qkv, *p_attn, *p_x1, *p_ffn;
    float *p_wq, *p_wp, *p_w1, *p_w2;
    cudaGetSymbolAddress((void**)&p_h,    g_h);
    cudaGetSymbolAddress((void**)&p_qkv,  g_qkv);
    cudaGetSymbolAddress((void**)&p_attn, g_attn);
    cudaGetSymbolAddress((void**)&p_x1,   g_x1);
    cudaGetSymbolAddress((void**)&p_ffn,  g_ffn);
    cudaGetSymbolAddress((void**)&p_wq,   g_wq);
    cudaGetSymbolAddress((void**)&p_wp,   g_wp);
    cudaGetSymbolAddress((void**)&p_w1,   g_w1);
    cudaGetSymbolAddress((void**)&p_w2,   g_w2);

    cudaFuncSetAttribute(tgemm_kernel<0, 1>,
        cudaFuncAttributeMaxDynamicSharedMemorySize, GEMM_SMEM);
    cudaFuncSetAttribute(tgemm_kernel<1, 0>,
        cudaFuncAttributeMaxDynamicSharedMemorySize, GEMM_SMEM);
    cudaFuncSetAttribute(tgemm_kernel<2, 1>,
        cudaFuncAttributeMaxDynamicSharedMemorySize, GEMM_SMEM);
    cudaFuncSetAttribute(attn_kernel,
        cudaFuncAttributeMaxDynamicSharedMemorySize, ATTN_SMEM);

    dim3 blk(256);

    {
        int n4;
        n4 = (D_MODEL * 3 * D_MODEL) / 4;
        tf32_trunc_kernel<<<(n4 + 255) / 256, blk>>>(wqkv, p_wq, n4);
        n4 = (D_MODEL * D_MODEL) / 4;
        tf32_trunc_kernel<<<(n4 + 255) / 256, blk>>>(wproj, p_wp, n4);
        n4 = (D_MODEL * 4 * D_MODEL) / 4;
        tf32_trunc_kernel<<<(n4 + 255) / 256, blk>>>(wfc1, p_w1, n4);
        n4 = (4 * D_MODEL * D_MODEL) / 4;
        tf32_trunc_kernel<<<(n4 + 255) / 256, blk>>>(wfc2, p_w2, n4);
    }

    rmsnorm_kernel<<<M_TOK, blk>>>(x, n1, p_h);

    tgemm_kernel<0, 1><<<dim3(3 * D_MODEL / BNT, M_TOK / BMT), blk, GEMM_SMEM>>>(
        p_h, p_wq, nullptr, p_qkv, M_TOK, 3 * D_MODEL, D_MODEL);

    attn_kernel<<<dim3(SEQ / 64, B_SZ * N_HEADS), dim3(128), ATTN_SMEM>>>(
        p_qkv, p_attn);

    tgemm_kernel<1, 0><<<dim3(D_MODEL / BNT, M_TOK / BMT), blk, GEMM_SMEM>>>(
        p_attn, p_wp, x, p_x1, M_TOK, D_MODEL, D_MODEL);

    rmsnorm_kernel<<<M_TOK, blk>>>(p_x1, n2, p_h);

    tgemm_kernel<2, 1><<<dim3(4 * D_MODEL / BNT, M_TOK / BMT), blk, GEMM_SMEM>>>(
        p_h, p_w1, nullptr, p_ffn, M_TOK, 4 * D_MODEL, D_MODEL);

    tgemm_kernel<1, 0><<<dim3(D_MODEL / BNT, M_TOK / BMT), blk, GEMM_SMEM>>>(
        p_ffn, p_w2, p_x1, out, M_TOK, D_MODEL, 4 * D_MODEL);
}

// round 7
// speedup vs baseline: 6.5921x; 1.0466x over previous
#include <cuda_runtime.h>
#include <math.h>
#include <stdint.h>

#define D_MODEL 1024
#define N_HEADS 16
#define HEAD_DIM 64
#define B_SZ 4
#define SEQ 2048
#define M_TOK (B_SZ * SEQ)

// ---------------- scratch ----------------
__device__ float g_h   [(size_t)M_TOK * D_MODEL];
__device__ float g_qkv [(size_t)M_TOK * 3 * D_MODEL];
__device__ float g_attn[(size_t)M_TOK * D_MODEL];
__device__ float g_x1  [(size_t)M_TOK * D_MODEL];
__device__ float g_ffn [(size_t)M_TOK * 4 * D_MODEL];
// tf32-truncated weights [K][N]
__device__ float g_wq [(size_t)D_MODEL * 3 * D_MODEL];
__device__ float g_wp [(size_t)D_MODEL * D_MODEL];
__device__ float g_w1 [(size_t)D_MODEL * 4 * D_MODEL];
__device__ float g_w2 [(size_t)4 * D_MODEL * D_MODEL];

// ------------------------------------------------------- common tf32 bits ---
__device__ __forceinline__ uint32_t f2tf32(float x) {
    uint32_t r;
    asm("cvt.rna.tf32.f32 %0, %1;" : "=r"(r) : "f"(x));
    return r;
}
__device__ __forceinline__ void mma_tf32(float* c, const uint32_t* a, const uint32_t* b) {
    asm volatile(
        "mma.sync.aligned.m16n8k8.row.col.f32.tf32.tf32.f32 "
        "{%0,%1,%2,%3}, {%4,%5,%6,%7}, {%8,%9}, {%0,%1,%2,%3};"
        : "+f"(c[0]), "+f"(c[1]), "+f"(c[2]), "+f"(c[3])
        : "r"(a[0]), "r"(a[1]), "r"(a[2]), "r"(a[3]), "r"(b[0]), "r"(b[1]));
}
__device__ __forceinline__ void cp_async16(uint32_t smem, const void* gmem) {
    asm volatile("cp.async.cg.shared.global [%0], [%1], 16;\n" ::"r"(smem), "l"(gmem));
}
__device__ __forceinline__ float gelu_exact(float v) {
    return 0.5f * v * (1.0f + erff(v * 0.70710678118654752f));
}

// -------------------------------------------------- tf32 truncation pass ---
__global__ void tf32_trunc_kernel(const float* __restrict__ in,
                                  float* __restrict__ out, int n4) {
    int i = blockIdx.x * blockDim.x + threadIdx.x;
    if (i >= n4) return;
    float4 v = reinterpret_cast<const float4*>(in)[i];
    uint4 u;
    u.x = f2tf32(v.x); u.y = f2tf32(v.y); u.z = f2tf32(v.z); u.w = f2tf32(v.w);
    reinterpret_cast<uint4*>(out)[i] = u;
}

// ------------------------------------------- RMSNorm (tf32-trunc output) ---
__global__ void rmsnorm_kernel(const float* __restrict__ x,
                               const float* __restrict__ scale,
                               float* __restrict__ out) {
    int row = blockIdx.x;
    int t = threadIdx.x;
    const float4* xr = reinterpret_cast<const float4*>(x + (size_t)row * D_MODEL);
    float4 v = xr[t];
    float ss = v.x * v.x + v.y * v.y + v.z * v.z + v.w * v.w;
    #pragma unroll
    for (int o = 16; o > 0; o >>= 1) ss += __shfl_xor_sync(0xffffffffu, ss, o);
    __shared__ float wsum[8];
    if ((t & 31) == 0) wsum[t >> 5] = ss;
    __syncthreads();
    if (t < 8) {
        float s2 = wsum[t];
        #pragma unroll
        for (int o = 4; o > 0; o >>= 1) s2 += __shfl_xor_sync(0xffu, s2, o);
        if (t == 0) wsum[0] = s2;
    }
    __syncthreads();
    float inv = rsqrtf(wsum[0] * (1.0f / D_MODEL) + 1e-8f);
    float4 s4 = reinterpret_cast<const float4*>(scale)[t];
    uint4 o4;
    o4.x = f2tf32(v.x * inv * s4.x);
    o4.y = f2tf32(v.y * inv * s4.y);
    o4.z = f2tf32(v.z * inv * s4.z);
    o4.w = f2tf32(v.w * inv * s4.w);
    reinterpret_cast<uint4*>(out + (size_t)row * D_MODEL)[t] = o4;
}

// ------------------------------------------------------- TF32 tensor GEMM ---
// 3-stage cp.async ring, ONE __syncthreads per k-tile, BKT=32.
#define BMT 128
#define BNT 128
#define BKT 32
#define ASTR 36     // banks: (36g+t)%32 = (4g+t) -> all 32 distinct
#define BSTR 136    // banks: (136t+g)%32 = (8t+g) -> all 32 distinct
#define A_STG (BMT * ASTR)   // 4608 floats
#define B_STG (BKT * BSTR)   // 4352 floats
#define GEMM_SMEM ((3 * (A_STG + B_STG)) * 4)

template <int EPI, int TRUNC>  // EPI: 0 none, 1 +residual, 2 gelu
__global__ __launch_bounds__(256, 2)
void tgemm_kernel(const float* __restrict__ A, const float* __restrict__ Bm,
                  const float* __restrict__ R, float* __restrict__ C,
                  int M, int N, int K) {
    extern __shared__ float dsm[];
    float* Asm = dsm;
    float* Bsm = dsm + 3 * A_STG;

    int tid = threadIdx.x;
    int warp = tid >> 5, lane = tid & 31;
    int group = lane >> 2, tig = lane & 3;
    int wm = warp >> 2, wn = warp & 3;
    int bm = blockIdx.y * BMT, bn = blockIdx.x * BNT;

    uint32_t sA = (uint32_t)__cvta_generic_to_shared(Asm);
    uint32_t sB = (uint32_t)__cvta_generic_to_shared(Bsm);

    auto load_stage = [&](int s, int k0) {
        uint32_t aS = sA + (uint32_t)(s * A_STG) * 4;
        uint32_t bS = sB + (uint32_t)(s * B_STG) * 4;
        #pragma unroll
        for (int i = 0; i < 4; i++) {
            int cid = tid + 256 * i;                 // 0..1023
            int ar = cid >> 3, ac = (cid & 7) * 4;   // A: 128 rows x 8 chunks
            cp_async16(aS + (uint32_t)(ar * ASTR + ac) * 4,
                       A + (size_t)(bm + ar) * K + k0 + ac);
            int br = cid >> 5, bc = (cid & 31) * 4;  // B: 32 rows x 32 chunks
            cp_async16(bS + (uint32_t)(br * BSTR + bc) * 4,
                       Bm + (size_t)(k0 + br) * N + bn + bc);
        }
    };

    float c[4][4][4] = {};
    int KT = K / BKT;

    load_stage(0, 0);
    asm volatile("cp.async.commit_group;\n" ::);
    load_stage(1, BKT);
    asm volatile("cp.async.commit_group;\n" ::);

    int s = 0, sn = 2;
    for (int kt = 0; kt < KT; kt++) {
        asm volatile("cp.async.wait_group 1;\n" ::);
        __syncthreads();
        if (kt + 2 < KT) load_stage(sn, (kt + 2) * BKT);
        asm volatile("cp.async.commit_group;\n" ::);

        const float* As = Asm + s * A_STG;
        const float* Bs = Bsm + s * B_STG;

        #pragma unroll
        for (int ks = 0; ks < BKT; ks += 8) {
            uint32_t af[4][4], bf[4][2];
            #pragma unroll
            for (int mt = 0; mt < 4; mt++) {
                int m = wm * 64 + mt * 16 + group;
                af[mt][0] = __float_as_uint(As[(m)     * ASTR + ks + tig]);
                af[mt][1] = __float_as_uint(As[(m + 8) * ASTR + ks + tig]);
                af[mt][2] = __float_as_uint(As[(m)     * ASTR + ks + tig + 4]);
                af[mt][3] = __float_as_uint(As[(m + 8) * ASTR + ks + tig + 4]);
            }
            #pragma unroll
            for (int nt = 0; nt < 4; nt++) {
                int n = wn * 32 + nt * 8 + group;
                bf[nt][0] = __float_as_uint(Bs[(ks + tig)     * BSTR + n]);
                bf[nt][1] = __float_as_uint(Bs[(ks + tig + 4) * BSTR + n]);
            }
            #pragma unroll
            for (int mt = 0; mt < 4; mt++)
                #pragma unroll
                for (int nt = 0; nt < 4; nt++)
                    mma_tf32(c[mt][nt], af[mt], bf[nt]);
        }
        s  = (s  == 2) ? 0 : s + 1;
        sn = (sn == 2) ? 0 : sn + 1;
    }

    #pragma unroll
    for (int mt = 0; mt < 4; mt++) {
        #pragma unroll
        for (int half = 0; half < 2; half++) {
            int row = bm + wm * 64 + mt * 16 + group + half * 8;
            float* Crow = C + (size_t)row * N;
            const float* Rrow = (EPI == 1) ? (R + (size_t)row * N) : nullptr;
            #pragma unroll
            for (int nt = 0; nt < 4; nt++) {
                int col = bn + wn * 32 + nt * 8 + tig * 2;
                float v0 = c[mt][nt][half * 2 + 0];
                float v1 = c[mt][nt][half * 2 + 1];
                if (EPI == 2) { v0 = gelu_exact(v0); v1 = gelu_exact(v1); }
                if (EPI == 1) {
                    float2 r2 = *reinterpret_cast<const float2*>(Rrow + col);
                    v0 += r2.x; v1 += r2.y;
                }
                if (TRUNC) {
                    v0 = __uint_as_float(f2tf32(v0));
                    v1 = __uint_as_float(f2tf32(v1));
                }
                *reinterpret_cast<float2*>(Crow + col) = make_float2(v0, v1);
            }
        }
    }
}

// ----------------------------------------- TF32 tensor flash attention -----
// Register-P: S-frag -> A-frag permutation done with warp shuffles.
// ONE __syncthreads per k-tile; 2-stage cp.async K/V double buffer.
#define KSTR 68
#define VSTR 72
#define K_STG (64 * KSTR)
#define V_STG (64 * VSTR)
#define ATTN_SMEM ((2 * (K_STG + V_STG)) * 4)

__global__ __launch_bounds__(128)
void attn_kernel(const float* __restrict__ qkv, float* __restrict__ out) {
    extern __shared__ float dsm[];
    float* Kst = dsm;
    float* Vst = dsm + 2 * K_STG;

    int bh = blockIdx.y;
    int b = bh >> 4, h = bh & 15;
    int q0 = blockIdx.x * 64;
    int tid = threadIdx.x;
    int w = tid >> 5, lane = tid & 31;
    int group = lane >> 2, tig = lane & 3;

    const size_t rs = 3 * D_MODEL;
    const float* qbase = qkv + (size_t)b * SEQ * rs + h * HEAD_DIM;
    const float* kbase = qbase + D_MODEL;
    const float* vbase = qbase + 2 * D_MODEL;

    uint32_t sK = (uint32_t)__cvta_generic_to_shared(Kst);
    uint32_t sV = (uint32_t)__cvta_generic_to_shared(Vst);
    int cr = tid >> 4, cc = (tid & 15) * 4;

    auto stage_kv = [&](int st, int k0) {
        uint32_t kS = sK + (uint32_t)(st * K_STG) * 4;
        uint32_t vS = sV + (uint32_t)(st * V_STG) * 4;
        #pragma unroll
        for (int rep = 0; rep < 8; rep++) {
            int r = rep * 8 + cr;
            cp_async16(kS + (uint32_t)(r * KSTR + cc) * 4,
                       kbase + (size_t)(k0 + r) * rs + cc);
            cp_async16(vS + (uint32_t)(r * VSTR + cc) * 4,
                       vbase + (size_t)(k0 + r) * rs + cc);
        }
        asm volatile("cp.async.commit_group;\n" ::);
    };

    uint32_t aq[8][4];
    {
        int r0 = q0 + w * 16 + group, r1 = r0 + 8;
        #pragma unroll
        for (int kf = 0; kf < 8; kf++) {
            int d = kf * 8 + tig;
            aq[kf][0] = __float_as_uint(0.125f * qbase[(size_t)r0 * rs + d]);
            aq[kf][1] = __float_as_uint(0.125f * qbase[(size_t)r1 * rs + d]);
            aq[kf][2] = __float_as_uint(0.125f * qbase[(size_t)r0 * rs + d + 4]);
            aq[kf][3] = __float_as_uint(0.125f * qbase[(size_t)r1 * rs + d + 4]);
        }
    }

    float o[8][4] = {};
    float mrow[2] = {-1e30f, -1e30f};
    float lrow[2] = {0.0f, 0.0f};

    stage_kv(0, 0);
    int cur = 0;

    for (int k0 = 0; k0 < SEQ; k0 += 64) {
        asm volatile("cp.async.wait_group 0;\n" ::);
        __syncthreads();   // stage `cur` ready; prior-iter V readers done
        if (k0 + 64 < SEQ) stage_kv(cur ^ 1, k0 + 64);

        float* Kc = Kst + cur * K_STG;
        float* Vc = Vst + cur * V_STG;

        // S = Q @ K^T
        float s[8][4] = {};
        #pragma unroll
        for (int kf = 0; kf < 8; kf++) {
            #pragma unroll
            for (int nf = 0; nf < 8; nf++) {
                uint32_t bfr[2];
                const float* kp = &Kc[(nf * 8 + group) * KSTR + kf * 8 + tig];
                bfr[0] = __float_as_uint(kp[0]);
                bfr[1] = __float_as_uint(kp[4]);
                mma_tf32(s[nf], aq[kf], bfr);
            }
        }

        // online softmax
        float al[2];
        #pragma unroll
        for (int r = 0; r < 2; r++) {
            float mx = -1e30f;
            #pragma unroll
            for (int nf = 0; nf < 8; nf++)
                mx = fmaxf(mx, fmaxf(s[nf][2 * r], s[nf][2 * r + 1]));
            mx = fmaxf(mx, __shfl_xor_sync(0xffffffffu, mx, 1));
            mx = fmaxf(mx, __shfl_xor_sync(0xffffffffu, mx, 2));
            float mn = fmaxf(mrow[r], mx);
            al[r] = __expf(mrow[r] - mn);
            float rsum = 0.0f;
            #pragma unroll
            for (int nf = 0; nf < 8; nf++) {
                float p0 = __expf(s[nf][2 * r]     - mn);
                float p1 = __expf(s[nf][2 * r + 1] - mn);
                s[nf][2 * r] = p0; s[nf][2 * r + 1] = p1;
                rsum += p0 + p1;
            }
            rsum += __shfl_xor_sync(0xffffffffu, rsum, 1);
            rsum += __shfl_xor_sync(0xffffffffu, rsum, 2);
            lrow[r] = lrow[r] * al[r] + rsum;
            mrow[r] = mn;
            #pragma unroll
            for (int nf = 0; nf < 8; nf++) {
                o[nf][2 * r]     *= al[r];
                o[nf][2 * r + 1] *= al[r];
            }
        }

        // O += P @ V ; A-frag of P built in-register via warp shuffles.
        // P col c lives in lane (group<<2)|(c>>1 & 3), frag index c&1.
        #pragma unroll
        for (int kc = 0; kc < 8; kc++) {
            uint32_t p0 = f2tf32(s[kc][0]), p1 = f2tf32(s[kc][1]);
            uint32_t p2 = f2tf32(s[kc][2]), p3 = f2tf32(s[kc][3]);
            int srcl = (group << 2) | (tig >> 1);   // cols kc*8 + tig
            uint32_t v0 = __shfl_sync(0xffffffffu, p0, srcl);
            uint32_t v1 = __shfl_sync(0xffffffffu, p1, srcl);
            uint32_t v2 = __shfl_sync(0xffffffffu, p2, srcl);
            uint32_t v3 = __shfl_sync(0xffffffffu, p3, srcl);
            uint32_t u0 = __shfl_sync(0xffffffffu, p0, srcl + 2);  // cols +4
            uint32_t u1 = __shfl_sync(0xffffffffu, p1, srcl + 2);
            uint32_t u2 = __shfl_sync(0xffffffffu, p2, srcl + 2);
            uint32_t u3 = __shfl_sync(0xffffffffu, p3, srcl + 2);
            bool odd = (tig & 1) != 0;
            uint32_t ap[4];
            ap[0] = odd ? v1 : v0;   // P(group,   kc*8+tig)
            ap[1] = odd ? v3 : v2;   // P(group+8, kc*8+tig)
            ap[2] = odd ? u1 : u0;   // P(group,   kc*8+tig+4)
            ap[3] = odd ? u3 : u2;   // P(group+8, kc*8+tig+4)
            #pragma unroll
            for (int nf = 0; nf < 8; nf++) {
                uint32_t bfr[2];
                const float* vp = &Vc[(kc * 8 + tig) * VSTR + nf * 8 + group];
                bfr[0] = __float_as_uint(vp[0]);
                bfr[1] = __float_as_uint(vp[4 * VSTR]);
                mma_tf32(o[nf], ap, bfr);
            }
        }
        cur ^= 1;
    }

    #pragma unroll
    for (int r = 0; r < 2; r++) {
        float inv = 1.0f / lrow[r];
        int row = q0 + w * 16 + group + 8 * r;
        float* orow = out + ((size_t)(b * SEQ + row)) * D_MODEL + h * HEAD_DIM;
        #pragma unroll
        for (int nf = 0; nf < 8; nf++) {
            int col = nf * 8 + 2 * tig;
            uint2 u = make_uint2(f2tf32(o[nf][2 * r] * inv),
                                 f2tf32(o[nf][2 * r + 1] * inv));
            *reinterpret_cast<uint2*>(orow + col) = u;
        }
    }
}

// ---------------------------------------------------------------- launch ----
extern "C" void kernel_launch(void* const* d_in, const int* in_sizes, int n_in,
                              void* d_out, int out_size) {
    const float* x     = (const float*)d_in[0];
    const float* n1    = (const float*)d_in[1];
    const float* wqkv  = (const float*)d_in[2];
    const float* wproj = (const float*)d_in[3];
    const float* n2    = (const float*)d_in[4];
    const float* wfc1  = (const float*)d_in[5];
    const float* wfc2  = (const float*)d_in[6];
    float* out = (float*)d_out;

    float *p_h, *p_qkv, *p_attn, *p_x1, *p_ffn;
    float *p_wq, *p_wp, *p_w1, *p_w2;
    cudaGetSymbolAddress((void**)&p_h,    g_h);
    cudaGetSymbolAddress((void**)&p_qkv,  g_qkv);
    cudaGetSymbolAddress((void**)&p_attn, g_attn);
    cudaGetSymbolAddress((void**)&p_x1,   g_x1);
    cudaGetSymbolAddress((void**)&p_ffn,  g_ffn);
    cudaGetSymbolAddress((void**)&p_wq,   g_wq);
    cudaGetSymbolAddress((void**)&p_wp,   g_wp);
    cudaGetSymbolAddress((void**)&p_w1,   g_w1);
    cudaGetSymbolAddress((void**)&p_w2,   g_w2);

    cudaFuncSetAttribute(tgemm_kernel<0, 1>,
        cudaFuncAttributeMaxDynamicSharedMemorySize, GEMM_SMEM);
    cudaFuncSetAttribute(tgemm_kernel<1, 0>,
        cudaFuncAttributeMaxDynamicSharedMemorySize, GEMM_SMEM);
    cudaFuncSetAttribute(tgemm_kernel<2, 1>,
        cudaFuncAttributeMaxDynamicSharedMemorySize, GEMM_SMEM);
    cudaFuncSetAttribute(attn_kernel,
        cudaFuncAttributeMaxDynamicSharedMemorySize, ATTN_SMEM);

    dim3 blk(256);

    {
        int n4;
        n4 = (D_MODEL * 3 * D_MODEL) / 4;
        tf32_trunc_kernel<<<(n4 + 255) / 256, blk>>>(wqkv, p_wq, n4);
        n4 = (D_MODEL * D_MODEL) / 4;
        tf32_trunc_kernel<<<(n4 + 255) / 256, blk>>>(wproj, p_wp, n4);
        n4 = (D_MODEL * 4 * D_MODEL) / 4;
        tf32_trunc_kernel<<<(n4 + 255) / 256, blk>>>(wfc1, p_w1, n4);
        n4 = (4 * D_MODEL * D_MODEL) / 4;
        tf32_trunc_kernel<<<(n4 + 255) / 256, blk>>>(wfc2, p_w2, n4);
    }

    rmsnorm_kernel<<<M_TOK, blk>>>(x, n1, p_h);

    tgemm_kernel<0, 1><<<dim3(3 * D_MODEL / BNT, M_TOK / BMT), blk, GEMM_SMEM>>>(
        p_h, p_wq, nullptr, p_qkv, M_TOK, 3 * D_MODEL, D_MODEL);

    attn_kernel<<<dim3(SEQ / 64, B_SZ * N_HEADS), dim3(128), ATTN_SMEM>>>(
        p_qkv, p_attn);

    tgemm_kernel<1, 0><<<dim3(D_MODEL / BNT, M_TOK / BMT), blk, GEMM_SMEM>>>(
        p_attn, p_wp, x, p_x1, M_TOK, D_MODEL, D_MODEL);

    rmsnorm_kernel<<<M_TOK, blk>>>(p_x1, n2, p_h);

    tgemm_kernel<2, 1><<<dim3(4 * D_MODEL / BNT, M_TOK / BMT), blk, GEMM_SMEM>>>(
        p_h, p_w1, nullptr, p_ffn, M_TOK, 4 * D_MODEL, D_MODEL);

    tgemm_kernel<1, 0><<<dim3(D_MODEL / BNT, M_TOK / BMT), blk, GEMM_SMEM>>>(
        p_ffn, p_w2, p_x1, out, M_TOK, D_MODEL, 4 * D_MODEL);
}

// round 8
// speedup vs baseline: 6.8263x; 1.0355x over previous
#include <cuda_runtime.h>
#include <math.h>
#include <stdint.h>

#define D_MODEL 1024
#define N_HEADS 16
#define HEAD_DIM 64
#define B_SZ 4
#define SEQ 2048
#define M_TOK (B_SZ * SEQ)

// ---------------- scratch ----------------
__device__ float g_h   [(size_t)M_TOK * D_MODEL];
__device__ float g_qkv [(size_t)M_TOK * 3 * D_MODEL];
__device__ float g_attn[(size_t)M_TOK * D_MODEL];
__device__ float g_x1  [(size_t)M_TOK * D_MODEL];
__device__ float g_ffn [(size_t)M_TOK * 4 * D_MODEL];
// tf32-truncated weights [K][N]
__device__ float g_wq [(size_t)D_MODEL * 3 * D_MODEL];
__device__ float g_wp [(size_t)D_MODEL * D_MODEL];
__device__ float g_w1 [(size_t)D_MODEL * 4 * D_MODEL];
__device__ float g_w2 [(size_t)4 * D_MODEL * D_MODEL];

// ------------------------------------------------------- common tf32 bits ---
__device__ __forceinline__ uint32_t f2tf32(float x) {
    uint32_t r;
    asm("cvt.rna.tf32.f32 %0, %1;" : "=r"(r) : "f"(x));
    return r;
}
__device__ __forceinline__ void mma_tf32(float* c, const uint32_t* a, const uint32_t* b) {
    asm volatile(
        "mma.sync.aligned.m16n8k8.row.col.f32.tf32.tf32.f32 "
        "{%0,%1,%2,%3}, {%4,%5,%6,%7}, {%8,%9}, {%0,%1,%2,%3};"
        : "+f"(c[0]), "+f"(c[1]), "+f"(c[2]), "+f"(c[3])
        : "r"(a[0]), "r"(a[1]), "r"(a[2]), "r"(a[3]), "r"(b[0]), "r"(b[1]));
}
__device__ __forceinline__ void ldsm_x4(uint32_t* r, uint32_t saddr) {
    asm volatile("ldmatrix.sync.aligned.m8n8.x4.shared.b16 {%0,%1,%2,%3}, [%4];"
        : "=r"(r[0]), "=r"(r[1]), "=r"(r[2]), "=r"(r[3]) : "r"(saddr));
}
__device__ __forceinline__ void cp_async16(uint32_t smem, const void* gmem) {
    asm volatile("cp.async.cg.shared.global [%0], [%1], 16;\n" ::"r"(smem), "l"(gmem));
}
__device__ __forceinline__ float gelu_exact(float v) {
    return 0.5f * v * (1.0f + erff(v * 0.70710678118654752f));
}

// -------------------------------------------------- tf32 truncation pass ---
__global__ void tf32_trunc_kernel(const float* __restrict__ in,
                                  float* __restrict__ out, int n4) {
    int i = blockIdx.x * blockDim.x + threadIdx.x;
    if (i >= n4) return;
    float4 v = reinterpret_cast<const float4*>(in)[i];
    uint4 u;
    u.x = f2tf32(v.x); u.y = f2tf32(v.y); u.z = f2tf32(v.z); u.w = f2tf32(v.w);
    reinterpret_cast<uint4*>(out)[i] = u;
}

// ------------------------------------------- RMSNorm (tf32-trunc output) ---
__global__ void rmsnorm_kernel(const float* __restrict__ x,
                               const float* __restrict__ scale,
                               float* __restrict__ out) {
    int row = blockIdx.x;
    int t = threadIdx.x;
    const float4* xr = reinterpret_cast<const float4*>(x + (size_t)row * D_MODEL);
    float4 v = xr[t];
    float ss = v.x * v.x + v.y * v.y + v.z * v.z + v.w * v.w;
    #pragma unroll
    for (int o = 16; o > 0; o >>= 1) ss += __shfl_xor_sync(0xffffffffu, ss, o);
    __shared__ float wsum[8];
    if ((t & 31) == 0) wsum[t >> 5] = ss;
    __syncthreads();
    if (t < 8) {
        float s2 = wsum[t];
        #pragma unroll
        for (int o = 4; o > 0; o >>= 1) s2 += __shfl_xor_sync(0xffu, s2, o);
        if (t == 0) wsum[0] = s2;
    }
    __syncthreads();
    float inv = rsqrtf(wsum[0] * (1.0f / D_MODEL) + 1e-8f);
    float4 s4 = reinterpret_cast<const float4*>(scale)[t];
    uint4 o4;
    o4.x = f2tf32(v.x * inv * s4.x);
    o4.y = f2tf32(v.y * inv * s4.y);
    o4.z = f2tf32(v.z * inv * s4.z);
    o4.w = f2tf32(v.w * inv * s4.w);
    reinterpret_cast<uint4*>(out + (size_t)row * D_MODEL)[t] = o4;
}

// ------------------------------------------------------- TF32 tensor GEMM ---
// 3-stage cp.async ring, one barrier per k-tile, ldmatrix A-frags.
#define BMT 128
#define BNT 128
#define BKT 32
#define ASTR 36     // 144B rows: ldmatrix banks 4i%32 conflict-free
#define BSTR 136
#define A_STG (BMT * ASTR)
#define B_STG (BKT * BSTR)
#define GEMM_SMEM ((3 * (A_STG + B_STG)) * 4)

template <int EPI, int TRUNC>  // EPI: 0 none, 1 +residual, 2 gelu
__global__ __launch_bounds__(256, 2)
void tgemm_kernel(const float* __restrict__ A, const float* __restrict__ Bm,
                  const float* __restrict__ R, float* __restrict__ C,
                  int M, int N, int K) {
    extern __shared__ float dsm[];
    float* Asm = dsm;
    float* Bsm = dsm + 3 * A_STG;

    int tid = threadIdx.x;
    int warp = tid >> 5, lane = tid & 31;
    int group = lane >> 2, tig = lane & 3;
    int wm = warp >> 2, wn = warp & 3;
    int bm = blockIdx.y * BMT, bn = blockIdx.x * BNT;

    uint32_t sA = (uint32_t)__cvta_generic_to_shared(Asm);
    uint32_t sB = (uint32_t)__cvta_generic_to_shared(Bsm);

    // ldmatrix per-lane offset: rows m0+(lane&15), col += 4 if lane>=16
    uint32_t a_lane_off =
        (uint32_t)(((wm * 64 + (lane & 15)) * ASTR + ((lane & 16) >> 2)) * 4);

    auto load_stage = [&](int s, int k0) {
        uint32_t aS = sA + (uint32_t)(s * A_STG) * 4;
        uint32_t bS = sB + (uint32_t)(s * B_STG) * 4;
        #pragma unroll
        for (int i = 0; i < 4; i++) {
            int cid = tid + 256 * i;
            int ar = cid >> 3, ac = (cid & 7) * 4;
            cp_async16(aS + (uint32_t)(ar * ASTR + ac) * 4,
                       A + (size_t)(bm + ar) * K + k0 + ac);
            int br = cid >> 5, bc = (cid & 31) * 4;
            cp_async16(bS + (uint32_t)(br * BSTR + bc) * 4,
                       Bm + (size_t)(k0 + br) * N + bn + bc);
        }
    };

    float c[4][4][4] = {};
    int KT = K / BKT;

    load_stage(0, 0);
    asm volatile("cp.async.commit_group;\n" ::);
    load_stage(1, BKT);
    asm volatile("cp.async.commit_group;\n" ::);

    int s = 0, sn = 2;
    for (int kt = 0; kt < KT; kt++) {
        asm volatile("cp.async.wait_group 1;\n" ::);
        __syncthreads();
        if (kt + 2 < KT) load_stage(sn, (kt + 2) * BKT);
        asm volatile("cp.async.commit_group;\n" ::);

        uint32_t aBase = sA + (uint32_t)(s * A_STG) * 4 + a_lane_off;
        const float* Bs = Bsm + s * B_STG;

        #pragma unroll
        for (int ks = 0; ks < BKT; ks += 8) {
            uint32_t af[4][4], bf[4][2];
            #pragma unroll
            for (int mt = 0; mt < 4; mt++)
                ldsm_x4(af[mt], aBase + (uint32_t)((mt * 16 * ASTR + ks) * 4));
            #pragma unroll
            for (int nt = 0; nt < 4; nt++) {
                int n = wn * 32 + nt * 8 + group;
                bf[nt][0] = __float_as_uint(Bs[(ks + tig)     * BSTR + n]);
                bf[nt][1] = __float_as_uint(Bs[(ks + tig + 4) * BSTR + n]);
            }
            #pragma unroll
            for (int mt = 0; mt < 4; mt++)
                #pragma unroll
                for (int nt = 0; nt < 4; nt++)
                    mma_tf32(c[mt][nt], af[mt], bf[nt]);
        }
        s  = (s  == 2) ? 0 : s + 1;
        sn = (sn == 2) ? 0 : sn + 1;
    }

    #pragma unroll
    for (int mt = 0; mt < 4; mt++) {
        #pragma unroll
        for (int half = 0; half < 2; half++) {
            int row = bm + wm * 64 + mt * 16 + group + half * 8;
            float* Crow = C + (size_t)row * N;
            const float* Rrow = (EPI == 1) ? (R + (size_t)row * N) : nullptr;
            #pragma unroll
            for (int nt = 0; nt < 4; nt++) {
                int col = bn + wn * 32 + nt * 8 + tig * 2;
                float v0 = c[mt][nt][half * 2 + 0];
                float v1 = c[mt][nt][half * 2 + 1];
                if (EPI == 2) { v0 = gelu_exact(v0); v1 = gelu_exact(v1); }
                if (EPI == 1) {
                    float2 r2 = *reinterpret_cast<const float2*>(Rrow + col);
                    v0 += r2.x; v1 += r2.y;
                }
                if (TRUNC) {
                    v0 = __uint_as_float(f2tf32(v0));
                    v1 = __uint_as_float(f2tf32(v1));
                }
                *reinterpret_cast<float2*>(Crow + col) = make_float2(v0, v1);
            }
        }
    }
}

// ----------------------------------------- TF32 tensor flash attention -----
// q-tile 128, 256 threads (8 warps x 16q). Register-P via shuffles.
#define KSTR 68
#define VSTR 72
#define K_STG (64 * KSTR)
#define V_STG (64 * VSTR)
#define ATTN_SMEM ((2 * (K_STG + V_STG)) * 4)

__global__ __launch_bounds__(256)
void attn_kernel(const float* __restrict__ qkv, float* __restrict__ out) {
    extern __shared__ float dsm[];
    float* Kst = dsm;
    float* Vst = dsm + 2 * K_STG;

    int bh = blockIdx.y;
    int b = bh >> 4, h = bh & 15;
    int q0 = blockIdx.x * 128;
    int tid = threadIdx.x;
    int w = tid >> 5, lane = tid & 31;
    int group = lane >> 2, tig = lane & 3;

    const size_t rs = 3 * D_MODEL;
    const float* qbase = qkv + (size_t)b * SEQ * rs + h * HEAD_DIM;
    const float* kbase = qbase + D_MODEL;
    const float* vbase = qbase + 2 * D_MODEL;

    uint32_t sK = (uint32_t)__cvta_generic_to_shared(Kst);
    uint32_t sV = (uint32_t)__cvta_generic_to_shared(Vst);
    int cr = tid >> 4, cc = (tid & 15) * 4;   // 16 rows x 16 chunks per pass

    auto stage_kv = [&](int st, int k0) {
        uint32_t kS = sK + (uint32_t)(st * K_STG) * 4;
        uint32_t vS = sV + (uint32_t)(st * V_STG) * 4;
        #pragma unroll
        for (int rep = 0; rep < 4; rep++) {
            int r = rep * 16 + cr;
            cp_async16(kS + (uint32_t)(r * KSTR + cc) * 4,
                       kbase + (size_t)(k0 + r) * rs + cc);
            cp_async16(vS + (uint32_t)(r * VSTR + cc) * 4,
                       vbase + (size_t)(k0 + r) * rs + cc);
        }
        asm volatile("cp.async.commit_group;\n" ::);
    };

    uint32_t aq[8][4];
    {
        int r0 = q0 + w * 16 + group, r1 = r0 + 8;
        #pragma unroll
        for (int kf = 0; kf < 8; kf++) {
            int d = kf * 8 + tig;
            aq[kf][0] = __float_as_uint(0.125f * qbase[(size_t)r0 * rs + d]);
            aq[kf][1] = __float_as_uint(0.125f * qbase[(size_t)r1 * rs + d]);
            aq[kf][2] = __float_as_uint(0.125f * qbase[(size_t)r0 * rs + d + 4]);
            aq[kf][3] = __float_as_uint(0.125f * qbase[(size_t)r1 * rs + d + 4]);
        }
    }

    float o[8][4] = {};
    float mrow[2] = {-1e30f, -1e30f};
    float lrow[2] = {0.0f, 0.0f};

    stage_kv(0, 0);
    int cur = 0;

    for (int k0 = 0; k0 < SEQ; k0 += 64) {
        asm volatile("cp.async.wait_group 0;\n" ::);
        __syncthreads();
        if (k0 + 64 < SEQ) stage_kv(cur ^ 1, k0 + 64);

        float* Kc = Kst + cur * K_STG;
        float* Vc = Vst + cur * V_STG;

        // S = Q @ K^T
        float s[8][4] = {};
        #pragma unroll
        for (int kf = 0; kf < 8; kf++) {
            #pragma unroll
            for (int nf = 0; nf < 8; nf++) {
                uint32_t bfr[2];
                const float* kp = &Kc[(nf * 8 + group) * KSTR + kf * 8 + tig];
                bfr[0] = __float_as_uint(kp[0]);
                bfr[1] = __float_as_uint(kp[4]);
                mma_tf32(s[nf], aq[kf], bfr);
            }
        }

        // online softmax
        float al[2];
        #pragma unroll
        for (int r = 0; r < 2; r++) {
            float mx = -1e30f;
            #pragma unroll
            for (int nf = 0; nf < 8; nf++)
                mx = fmaxf(mx, fmaxf(s[nf][2 * r], s[nf][2 * r + 1]));
            mx = fmaxf(mx, __shfl_xor_sync(0xffffffffu, mx, 1));
            mx = fmaxf(mx, __shfl_xor_sync(0xffffffffu, mx, 2));
            float mn = fmaxf(mrow[r], mx);
            al[r] = __expf(mrow[r] - mn);
            float rsum = 0.0f;
            #pragma unroll
            for (int nf = 0; nf < 8; nf++) {
                float p0 = __expf(s[nf][2 * r]     - mn);
                float p1 = __expf(s[nf][2 * r + 1] - mn);
                s[nf][2 * r] = p0; s[nf][2 * r + 1] = p1;
                rsum += p0 + p1;
            }
            rsum += __shfl_xor_sync(0xffffffffu, rsum, 1);
            rsum += __shfl_xor_sync(0xffffffffu, rsum, 2);
            lrow[r] = lrow[r] * al[r] + rsum;
            mrow[r] = mn;
            #pragma unroll
            for (int nf = 0; nf < 8; nf++) {
                o[nf][2 * r]     *= al[r];
                o[nf][2 * r + 1] *= al[r];
            }
        }

        // O += P @ V ; register-P via shuffles
        #pragma unroll
        for (int kc = 0; kc < 8; kc++) {
            uint32_t p0 = f2tf32(s[kc][0]), p1 = f2tf32(s[kc][1]);
            uint32_t p2 = f2tf32(s[kc][2]), p3 = f2tf32(s[kc][3]);
            int srcl = (group << 2) | (tig >> 1);
            uint32_t v0 = __shfl_sync(0xffffffffu, p0, srcl);
            uint32_t v1 = __shfl_sync(0xffffffffu, p1, srcl);
            uint32_t v2 = __shfl_sync(0xffffffffu, p2, srcl);
            uint32_t v3 = __shfl_sync(0xffffffffu, p3, srcl);
            uint32_t u0 = __shfl_sync(0xffffffffu, p0, srcl + 2);
            uint32_t u1 = __shfl_sync(0xffffffffu, p1, srcl + 2);
            uint32_t u2 = __shfl_sync(0xffffffffu, p2, srcl + 2);
            uint32_t u3 = __shfl_sync(0xffffffffu, p3, srcl + 2);
            bool odd = (tig & 1) != 0;
            uint32_t ap[4];
            ap[0] = odd ? v1 : v0;
            ap[1] = odd ? v3 : v2;
            ap[2] = odd ? u1 : u0;
            ap[3] = odd ? u3 : u2;
            #pragma unroll
            for (int nf = 0; nf < 8; nf++) {
                uint32_t bfr[2];
                const float* vp = &Vc[(kc * 8 + tig) * VSTR + nf * 8 + group];
                bfr[0] = __float_as_uint(vp[0]);
                bfr[1] = __float_as_uint(vp[4 * VSTR]);
                mma_tf32(o[nf], ap, bfr);
            }
        }
        cur ^= 1;
    }

    #pragma unroll
    for (int r = 0; r < 2; r++) {
        float inv = 1.0f / lrow[r];
        int row = q0 + w * 16 + group + 8 * r;
        float* orow = out + ((size_t)(b * SEQ + row)) * D_MODEL + h * HEAD_DIM;
        #pragma unroll
        for (int nf = 0; nf < 8; nf++) {
            int col = nf * 8 + 2 * tig;
            uint2 u = make_uint2(f2tf32(o[nf][2 * r] * inv),
                                 f2tf32(o[nf][2 * r + 1] * inv));
            *reinterpret_cast<uint2*>(orow + col) = u;
        }
    }
}

// ---------------------------------------------------------------- launch ----
extern "C" void kernel_launch(void* const* d_in, const int* in_sizes, int n_in,
                              void* d_out, int out_size) {
    const float* x     = (const float*)d_in[0];
    const float* n1    = (const float*)d_in[1];
    const float* wqkv  = (const float*)d_in[2];
    const float* wproj = (const float*)d_in[3];
    const float* n2    = (const float*)d_in[4];
    const float* wfc1  = (const float*)d_in[5];
    const float* wfc2  = (const float*)d_in[6];
    float* out = (float*)d_out;

    float *p_h, *p_qkv, *p_attn, *p_x1, *p_ffn;
    float *p_wq, *p_wp, *p_w1, *p_w2;
    cudaGetSymbolAddress((void**)&p_h,    g_h);
    cudaGetSymbolAddress((void**)&p_qkv,  g_qkv);
    cudaGetSymbolAddress((void**)&p_attn, g_attn);
    cudaGetSymbolAddress((void**)&p_x1,   g_x1);
    cudaGetSymbolAddress((void**)&p_ffn,  g_ffn);
    cudaGetSymbolAddress((void**)&p_wq,   g_wq);
    cudaGetSymbolAddress((void**)&p_wp,   g_wp);
    cudaGetSymbolAddress((void**)&p_w1,   g_w1);
    cudaGetSymbolAddress((void**)&p_w2,   g_w2);

    cudaFuncSetAttribute(tgemm_kernel<0, 1>,
        cudaFuncAttributeMaxDynamicSharedMemorySize, GEMM_SMEM);
    cudaFuncSetAttribute(tgemm_kernel<1, 0>,
        cudaFuncAttributeMaxDynamicSharedMemorySize, GEMM_SMEM);
    cudaFuncSetAttribute(tgemm_kernel<2, 1>,
        cudaFuncAttributeMaxDynamicSharedMemorySize, GEMM_SMEM);
    cudaFuncSetAttribute(attn_kernel,
        cudaFuncAttributeMaxDynamicSharedMemorySize, ATTN_SMEM);

    dim3 blk(256);

    {
        int n4;
        n4 = (D_MODEL * 3 * D_MODEL) / 4;
        tf32_trunc_kernel<<<(n4 + 255) / 256, blk>>>(wqkv, p_wq, n4);
        n4 = (D_MODEL * D_MODEL) / 4;
        tf32_trunc_kernel<<<(n4 + 255) / 256, blk>>>(wproj, p_wp, n4);
        n4 = (D_MODEL * 4 * D_MODEL) / 4;
        tf32_trunc_kernel<<<(n4 + 255) / 256, blk>>>(wfc1, p_w1, n4);
        n4 = (4 * D_MODEL * D_MODEL) / 4;
        tf32_trunc_kernel<<<(n4 + 255) / 256, blk>>>(wfc2, p_w2, n4);
    }

    rmsnorm_kernel<<<M_TOK, blk>>>(x, n1, p_h);

    tgemm_kernel<0, 1><<<dim3(3 * D_MODEL / BNT, M_TOK / BMT), blk, GEMM_SMEM>>>(
        p_h, p_wq, nullptr, p_qkv, M_TOK, 3 * D_MODEL, D_MODEL);

    attn_kernel<<<dim3(SEQ / 128, B_SZ * N_HEADS), dim3(256), ATTN_SMEM>>>(
        p_qkv, p_attn);

    tgemm_kernel<1, 0><<<dim3(D_MODEL / BNT, M_TOK / BMT), blk, GEMM_SMEM>>>(
        p_attn, p_wp, x, p_x1, M_TOK, D_MODEL, D_MODEL);

    rmsnorm_kernel<<<M_TOK, blk>>>(p_x1, n2, p_h);

    tgemm_kernel<2, 1><<<dim3(4 * D_MODEL / BNT, M_TOK / BMT), blk, GEMM_SMEM>>>(
        p_h, p_w1, nullptr, p_ffn, M_TOK, 4 * D_MODEL, D_MODEL);

    tgemm_kernel<1, 0><<<dim3(D_MODEL / BNT, M_TOK / BMT), blk, GEMM_SMEM>>>(
        p_ffn, p_w2, p_x1, out, M_TOK, D_MODEL, 4 * D_MODEL);
}

// round 9
// speedup vs baseline: 7.1606x; 1.0490x over previous
#include <cuda_runtime.h>
#include <math.h>
#include <stdint.h>

#define D_MODEL 1024
#define N_HEADS 16
#define HEAD_DIM 64
#define B_SZ 4
#define SEQ 2048
#define M_TOK (B_SZ * SEQ)

// ---------------- scratch ----------------
__device__ float g_h   [(size_t)M_TOK * D_MODEL];
__device__ float g_qkv [(size_t)M_TOK * 3 * D_MODEL];
__device__ float g_attn[(size_t)M_TOK * D_MODEL];
__device__ float g_x1  [(size_t)M_TOK * D_MODEL];
__device__ float g_ffn [(size_t)M_TOK * 4 * D_MODEL];
// tf32-truncated, TRANSPOSED weights [N][K]
__device__ float g_wq [(size_t)3 * D_MODEL * D_MODEL];
__device__ float g_wp [(size_t)D_MODEL * D_MODEL];
__device__ float g_w1 [(size_t)4 * D_MODEL * D_MODEL];
__device__ float g_w2 [(size_t)D_MODEL * 4 * D_MODEL];

// ------------------------------------------------------- common tf32 bits ---
__device__ __forceinline__ uint32_t f2tf32(float x) {
    uint32_t r;
    asm("cvt.rna.tf32.f32 %0, %1;" : "=r"(r) : "f"(x));
    return r;
}
__device__ __forceinline__ void mma_tf32(float* c, const uint32_t* a, const uint32_t* b) {
    asm volatile(
        "mma.sync.aligned.m16n8k8.row.col.f32.tf32.tf32.f32 "
        "{%0,%1,%2,%3}, {%4,%5,%6,%7}, {%8,%9}, {%0,%1,%2,%3};"
        : "+f"(c[0]), "+f"(c[1]), "+f"(c[2]), "+f"(c[3])
        : "r"(a[0]), "r"(a[1]), "r"(a[2]), "r"(a[3]), "r"(b[0]), "r"(b[1]));
}
__device__ __forceinline__ void ldsm_x4(uint32_t* r, uint32_t saddr) {
    asm volatile("ldmatrix.sync.aligned.m8n8.x4.shared.b16 {%0,%1,%2,%3}, [%4];"
        : "=r"(r[0]), "=r"(r[1]), "=r"(r[2]), "=r"(r[3]) : "r"(saddr));
}
__device__ __forceinline__ void cp_async16(uint32_t smem, const void* gmem) {
    asm volatile("cp.async.cg.shared.global [%0], [%1], 16;\n" ::"r"(smem), "l"(gmem));
}
__device__ __forceinline__ float gelu_exact(float v) {
    return 0.5f * v * (1.0f + erff(v * 0.70710678118654752f));
}

// --------------------------------------- weight transpose + tf32 trunc -----
// W[K][N] -> WT[N][K], tf32-truncated
__global__ void wtrans_kernel(const float* __restrict__ W, float* __restrict__ WT,
                              int K, int N) {
    __shared__ float t[32][33];
    int k0 = blockIdx.y * 32, n0 = blockIdx.x * 32;
    int tx = threadIdx.x, ty = threadIdx.y;  // 32 x 8
    #pragma unroll
    for (int i = 0; i < 4; i++)
        t[ty + i * 8][tx] = W[(size_t)(k0 + ty + i * 8) * N + n0 + tx];
    __syncthreads();
    #pragma unroll
    for (int i = 0; i < 4; i++) {
        float v = t[tx][ty + i * 8];
        WT[(size_t)(n0 + ty + i * 8) * K + k0 + tx] = __uint_as_float(f2tf32(v));
    }
}

// ------------------------------------------- RMSNorm (tf32-trunc output) ---
__global__ void rmsnorm_kernel(const float* __restrict__ x,
                               const float* __restrict__ scale,
                               float* __restrict__ out) {
    int row = blockIdx.x;
    int t = threadIdx.x;
    const float4* xr = reinterpret_cast<const float4*>(x + (size_t)row * D_MODEL);
    float4 v = xr[t];
    float ss = v.x * v.x + v.y * v.y + v.z * v.z + v.w * v.w;
    #pragma unroll
    for (int o = 16; o > 0; o >>= 1) ss += __shfl_xor_sync(0xffffffffu, ss, o);
    __shared__ float wsum[8];
    if ((t & 31) == 0) wsum[t >> 5] = ss;
    __syncthreads();
    if (t < 8) {
        float s2 = wsum[t];
        #pragma unroll
        for (int o = 4; o > 0; o >>= 1) s2 += __shfl_xor_sync(0xffu, s2, o);
        if (t == 0) wsum[0] = s2;
    }
    __syncthreads();
    float inv = rsqrtf(wsum[0] * (1.0f / D_MODEL) + 1e-8f);
    float4 s4 = reinterpret_cast<const float4*>(scale)[t];
    uint4 o4;
    o4.x = f2tf32(v.x * inv * s4.x);
    o4.y = f2tf32(v.y * inv * s4.y);
    o4.z = f2tf32(v.z * inv * s4.z);
    o4.w = f2tf32(v.w * inv * s4.w);
    reinterpret_cast<uint4*>(out + (size_t)row * D_MODEL)[t] = o4;
}

// ------------------------------------------------------- TF32 tensor GEMM ---
// A[M][K], Bt[N][K] both k-contiguous; ldmatrix for A AND B fragments.
#define BMT 128
#define BNT 128
#define BKT 32
#define TSTR 36     // row stride (floats) for both tiles; 144B rows
#define T_STG (128 * TSTR)
#define GEMM_SMEM ((3 * 2 * T_STG) * 4)

template <int EPI, int TRUNC>  // EPI: 0 none, 1 +residual, 2 gelu
__global__ __launch_bounds__(256, 2)
void tgemm_kernel(const float* __restrict__ A, const float* __restrict__ Bt,
                  const float* __restrict__ R, float* __restrict__ C,
                  int M, int N, int K) {
    extern __shared__ float dsm[];
    float* Asm = dsm;                  // 3 stages x T_STG
    float* Bsm = dsm + 3 * T_STG;      // 3 stages x T_STG

    int tid = threadIdx.x;
    int warp = tid >> 5, lane = tid & 31;
    int group = lane >> 2, tig = lane & 3;
    int wm = warp >> 2, wn = warp & 3;
    int bm = blockIdx.y * BMT, bn = blockIdx.x * BNT;

    uint32_t sA = (uint32_t)__cvta_generic_to_shared(Asm);
    uint32_t sB = (uint32_t)__cvta_generic_to_shared(Bsm);

    // A ldmatrix lanes: 0-15 rows m0+(lane&15) @ks, 16-31 same rows @ks+4
    uint32_t a_lane_off =
        (uint32_t)(((wm * 64 + (lane & 15)) * TSTR + ((lane & 16) >> 2)) * 4);
    // B ldmatrix lanes: row_off=(lane&7)+((lane>>4)&1)*8 ; col_off=((lane>>3)&1)*4
    int b_row_off = (lane & 7) + ((lane >> 4) & 1) * 8;
    int b_col_off = ((lane >> 3) & 1) * 4;
    uint32_t b_lane_off =
        (uint32_t)(((wn * 32 + b_row_off) * TSTR + b_col_off) * 4);

    auto load_stage = [&](int s, int k0) {
        uint32_t aS = sA + (uint32_t)(s * T_STG) * 4;
        uint32_t bS = sB + (uint32_t)(s * T_STG) * 4;
        #pragma unroll
        for (int i = 0; i < 4; i++) {
            int cid = tid + 256 * i;                 // 0..1023
            int r = cid >> 3, c4 = (cid & 7) * 4;    // 128 rows x 8 chunks
            cp_async16(aS + (uint32_t)(r * TSTR + c4) * 4,
                       A + (size_t)(bm + r) * K + k0 + c4);
            cp_async16(bS + (uint32_t)(r * TSTR + c4) * 4,
                       Bt + (size_t)(bn + r) * K + k0 + c4);
        }
    };

    float c[4][4][4] = {};
    int KT = K / BKT;

    load_stage(0, 0);
    asm volatile("cp.async.commit_group;\n" ::);
    load_stage(1, BKT);
    asm volatile("cp.async.commit_group;\n" ::);

    int s = 0, sn = 2;
    for (int kt = 0; kt < KT; kt++) {
        asm volatile("cp.async.wait_group 1;\n" ::);
        __syncthreads();
        if (kt + 2 < KT) load_stage(sn, (kt + 2) * BKT);
        asm volatile("cp.async.commit_group;\n" ::);

        uint32_t aBase = sA + (uint32_t)(s * T_STG) * 4 + a_lane_off;
        uint32_t bBase = sB + (uint32_t)(s * T_STG) * 4 + b_lane_off;

        #pragma unroll
        for (int ks = 0; ks < BKT; ks += 8) {
            uint32_t af[4][4], bf[4][2];
            #pragma unroll
            for (int mt = 0; mt < 4; mt++)
                ldsm_x4(af[mt], aBase + (uint32_t)((mt * 16 * TSTR + ks) * 4));
            #pragma unroll
            for (int ntp = 0; ntp < 2; ntp++) {
                uint32_t bq[4];
                ldsm_x4(bq, bBase + (uint32_t)((ntp * 16 * TSTR + ks) * 4));
                bf[2 * ntp][0] = bq[0]; bf[2 * ntp][1] = bq[1];
                bf[2 * ntp + 1][0] = bq[2]; bf[2 * ntp + 1][1] = bq[3];
            }
            #pragma unroll
            for (int mt = 0; mt < 4; mt++)
                #pragma unroll
                for (int nt = 0; nt < 4; nt++)
                    mma_tf32(c[mt][nt], af[mt], bf[nt]);
        }
        s  = (s  == 2) ? 0 : s + 1;
        sn = (sn == 2) ? 0 : sn + 1;
    }

    #pragma unroll
    for (int mt = 0; mt < 4; mt++) {
        #pragma unroll
        for (int half = 0; half < 2; half++) {
            int row = bm + wm * 64 + mt * 16 + group + half * 8;
            float* Crow = C + (size_t)row * N;
            const float* Rrow = (EPI == 1) ? (R + (size_t)row * N) : nullptr;
            #pragma unroll
            for (int nt = 0; nt < 4; nt++) {
                int col = bn + wn * 32 + nt * 8 + tig * 2;
                float v0 = c[mt][nt][half * 2 + 0];
                float v1 = c[mt][nt][half * 2 + 1];
                if (EPI == 2) { v0 = gelu_exact(v0); v1 = gelu_exact(v1); }
                if (EPI == 1) {
                    float2 r2 = *reinterpret_cast<const float2*>(Rrow + col);
                    v0 += r2.x; v1 += r2.y;
                }
                if (TRUNC) {
                    v0 = __uint_as_float(f2tf32(v0));
                    v1 = __uint_as_float(f2tf32(v1));
                }
                *reinterpret_cast<float2*>(Crow + col) = make_float2(v0, v1);
            }
        }
    }
}

// ----------------------------------------- TF32 tensor flash attention -----
// q-tile 128, 256 threads. K-fragments via ldmatrix; register-P via shuffles.
#define KSTR 68
#define VSTR 72
#define K_STG (64 * KSTR)
#define V_STG (64 * VSTR)
#define ATTN_SMEM ((2 * (K_STG + V_STG)) * 4)

__global__ __launch_bounds__(256)
void attn_kernel(const float* __restrict__ qkv, float* __restrict__ out) {
    extern __shared__ float dsm[];
    float* Kst = dsm;
    float* Vst = dsm + 2 * K_STG;

    int bh = blockIdx.y;
    int b = bh >> 4, h = bh & 15;
    int q0 = blockIdx.x * 128;
    int tid = threadIdx.x;
    int w = tid >> 5, lane = tid & 31;
    int group = lane >> 2, tig = lane & 3;

    const size_t rs = 3 * D_MODEL;
    const float* qbase = qkv + (size_t)b * SEQ * rs + h * HEAD_DIM;
    const float* kbase = qbase + D_MODEL;
    const float* vbase = qbase + 2 * D_MODEL;

    uint32_t sK = (uint32_t)__cvta_generic_to_shared(Kst);
    uint32_t sV = (uint32_t)__cvta_generic_to_shared(Vst);
    int cr = tid >> 4, cc = (tid & 15) * 4;

    // K ldmatrix lane offsets (rows = kseq, cols = d)
    int k_row_off = (lane & 7) + ((lane >> 4) & 1) * 8;
    int k_col_off = ((lane >> 3) & 1) * 4;
    uint32_t k_lane_off = (uint32_t)((k_row_off * KSTR + k_col_off) * 4);

    auto stage_kv = [&](int st, int k0) {
        uint32_t kS = sK + (uint32_t)(st * K_STG) * 4;
        uint32_t vS = sV + (uint32_t)(st * V_STG) * 4;
        #pragma unroll
        for (int rep = 0; rep < 4; rep++) {
            int r = rep * 16 + cr;
            cp_async16(kS + (uint32_t)(r * KSTR + cc) * 4,
                       kbase + (size_t)(k0 + r) * rs + cc);
            cp_async16(vS + (uint32_t)(r * VSTR + cc) * 4,
                       vbase + (size_t)(k0 + r) * rs + cc);
        }
        asm volatile("cp.async.commit_group;\n" ::);
    };

    uint32_t aq[8][4];
    {
        int r0 = q0 + w * 16 + group, r1 = r0 + 8;
        #pragma unroll
        for (int kf = 0; kf < 8; kf++) {
            int d = kf * 8 + tig;
            aq[kf][0] = __float_as_uint(0.125f * qbase[(size_t)r0 * rs + d]);
            aq[kf][1] = __float_as_uint(0.125f * qbase[(size_t)r1 * rs + d]);
            aq[kf][2] = __float_as_uint(0.125f * qbase[(size_t)r0 * rs + d + 4]);
            aq[kf][3] = __float_as_uint(0.125f * qbase[(size_t)r1 * rs + d + 4]);
        }
    }

    float o[8][4] = {};
    float mrow[2] = {-1e30f, -1e30f};
    float lrow[2] = {0.0f, 0.0f};

    stage_kv(0, 0);
    int cur = 0;

    for (int k0 = 0; k0 < SEQ; k0 += 64) {
        asm volatile("cp.async.wait_group 0;\n" ::);
        __syncthreads();
        if (k0 + 64 < SEQ) stage_kv(cur ^ 1, k0 + 64);

        uint32_t kBase = sK + (uint32_t)(cur * K_STG) * 4 + k_lane_off;
        float* Vc = Vst + cur * V_STG;

        // S = Q @ K^T  (K-fragments via ldmatrix.x4: covers nf pair)
        float s[8][4] = {};
        #pragma unroll
        for (int kf = 0; kf < 8; kf++) {
            #pragma unroll
            for (int np = 0; np < 4; np++) {
                uint32_t bq[4];
                ldsm_x4(bq, kBase + (uint32_t)((np * 16 * KSTR + kf * 8) * 4));
                mma_tf32(s[2 * np],     aq[kf], &bq[0]);
                mma_tf32(s[2 * np + 1], aq[kf], &bq[2]);
            }
        }

        // online softmax
        float al[2];
        #pragma unroll
        for (int r = 0; r < 2; r++) {
            float mx = -1e30f;
            #pragma unroll
            for (int nf = 0; nf < 8; nf++)
                mx = fmaxf(mx, fmaxf(s[nf][2 * r], s[nf][2 * r + 1]));
            mx = fmaxf(mx, __shfl_xor_sync(0xffffffffu, mx, 1));
            mx = fmaxf(mx, __shfl_xor_sync(0xffffffffu, mx, 2));
            float mn = fmaxf(mrow[r], mx);
            al[r] = __expf(mrow[r] - mn);
            float rsum = 0.0f;
            #pragma unroll
            for (int nf = 0; nf < 8; nf++) {
                float p0 = __expf(s[nf][2 * r]     - mn);
                float p1 = __expf(s[nf][2 * r + 1] - mn);
                s[nf][2 * r] = p0; s[nf][2 * r + 1] = p1;
                rsum += p0 + p1;
            }
            rsum += __shfl_xor_sync(0xffffffffu, rsum, 1);
            rsum += __shfl_xor_sync(0xffffffffu, rsum, 2);
            lrow[r] = lrow[r] * al[r] + rsum;
            mrow[r] = mn;
            #pragma unroll
            for (int nf = 0; nf < 8; nf++) {
                o[nf][2 * r]     *= al[r];
                o[nf][2 * r + 1] *= al[r];
            }
        }

        // O += P @ V ; register-P via shuffles
        #pragma unroll
        for (int kc = 0; kc < 8; kc++) {
            uint32_t p0 = f2tf32(s[kc][0]), p1 = f2tf32(s[kc][1]);
            uint32_t p2 = f2tf32(s[kc][2]), p3 = f2tf32(s[kc][3]);
            int srcl = (group << 2) | (tig >> 1);
            uint32_t v0 = __shfl_sync(0xffffffffu, p0, srcl);
            uint32_t v1 = __shfl_sync(0xffffffffu, p1, srcl);
            uint32_t v2 = __shfl_sync(0xffffffffu, p2, srcl);
            uint32_t v3 = __shfl_sync(0xffffffffu, p3, srcl);
            uint32_t u0 = __shfl_sync(0xffffffffu, p0, srcl + 2);
            uint32_t u1 = __shfl_sync(0xffffffffu, p1, srcl + 2);
            uint32_t u2 = __shfl_sync(0xffffffffu, p2, srcl + 2);
            uint32_t u3 = __shfl_sync(0xffffffffu, p3, srcl + 2);
            bool odd = (tig & 1) != 0;
            uint32_t ap[4];
            ap[0] = odd ? v1 : v0;
            ap[1] = odd ? v3 : v2;
            ap[2] = odd ? u1 : u0;
            ap[3] = odd ? u3 : u2;
            #pragma unroll
            for (int nf = 0; nf < 8; nf++) {
                uint32_t bfr[2];
                const float* vp = &Vc[(kc * 8 + tig) * VSTR + nf * 8 + group];
                bfr[0] = __float_as_uint(vp[0]);
                bfr[1] = __float_as_uint(vp[4 * VSTR]);
                mma_tf32(o[nf], ap, bfr);
            }
        }
        cur ^= 1;
    }

    #pragma unroll
    for (int r = 0; r < 2; r++) {
        float inv = 1.0f / lrow[r];
        int row = q0 + w * 16 + group + 8 * r;
        float* orow = out + ((size_t)(b * SEQ + row)) * D_MODEL + h * HEAD_DIM;
        #pragma unroll
        for (int nf = 0; nf < 8; nf++) {
            int col = nf * 8 + 2 * tig;
            uint2 u = make_uint2(f2tf32(o[nf][2 * r] * inv),
                                 f2tf32(o[nf][2 * r + 1] * inv));
            *reinterpret_cast<uint2*>(orow + col) = u;
        }
    }
}

// ---------------------------------------------------------------- launch ----
extern "C" void kernel_launch(void* const* d_in, const int* in_sizes, int n_in,
                              void* d_out, int out_size) {
    const float* x     = (const float*)d_in[0];
    const float* n1    = (const float*)d_in[1];
    const float* wqkv  = (const float*)d_in[2];
    const float* wproj = (const float*)d_in[3];
    const float* n2    = (const float*)d_in[4];
    const float* wfc1  = (const float*)d_in[5];
    const float* wfc2  = (const float*)d_in[6];
    float* out = (float*)d_out;

    float *p_h, *p_qkv, *p_attn, *p_x1, *p_ffn;
    float *p_wq, *p_wp, *p_w1, *p_w2;
    cudaGetSymbolAddress((void**)&p_h,    g_h);
    cudaGetSymbolAddress((void**)&p_qkv,  g_qkv);
    cudaGetSymbolAddress((void**)&p_attn, g_attn);
    cudaGetSymbolAddress((void**)&p_x1,   g_x1);
    cudaGetSymbolAddress((void**)&p_ffn,  g_ffn);
    cudaGetSymbolAddress((void**)&p_wq,   g_wq);
    cudaGetSymbolAddress((void**)&p_wp,   g_wp);
    cudaGetSymbolAddress((void**)&p_w1,   g_w1);
    cudaGetSymbolAddress((void**)&p_w2,   g_w2);

    cudaFuncSetAttribute(tgemm_kernel<0, 1>,
        cudaFuncAttributeMaxDynamicSharedMemorySize, GEMM_SMEM);
    cudaFuncSetAttribute(tgemm_kernel<1, 0>,
        cudaFuncAttributeMaxDynamicSharedMemorySize, GEMM_SMEM);
    cudaFuncSetAttribute(tgemm_kernel<2, 1>,
        cudaFuncAttributeMaxDynamicSharedMemorySize, GEMM_SMEM);
    cudaFuncSetAttribute(attn_kernel,
        cudaFuncAttributeMaxDynamicSharedMemorySize, ATTN_SMEM);

    dim3 tb(32, 8);

    // weight transpose + tf32 trunc:  W[K][N] -> WT[N][K]
    wtrans_kernel<<<dim3(3 * D_MODEL / 32, D_MODEL / 32), tb>>>(wqkv, p_wq, D_MODEL, 3 * D_MODEL);
    wtrans_kernel<<<dim3(D_MODEL / 32, D_MODEL / 32), tb>>>(wproj, p_wp, D_MODEL, D_MODEL);
    wtrans_kernel<<<dim3(4 * D_MODEL / 32, D_MODEL / 32), tb>>>(wfc1, p_w1, D_MODEL, 4 * D_MODEL);
    wtrans_kernel<<<dim3(D_MODEL / 32, 4 * D_MODEL / 32), tb>>>(wfc2, p_w2, 4 * D_MODEL, D_MODEL);

    rmsnorm_kernel<<<M_TOK, 256>>>(x, n1, p_h);

    tgemm_kernel<0, 1><<<dim3(3 * D_MODEL / BNT, M_TOK / BMT), 256, GEMM_SMEM>>>(
        p_h, p_wq, nullptr, p_qkv, M_TOK, 3 * D_MODEL, D_MODEL);

    attn_kernel<<<dim3(SEQ / 128, B_SZ * N_HEADS), dim3(256), ATTN_SMEM>>>(
        p_qkv, p_attn);

    tgemm_kernel<1, 0><<<dim3(D_MODEL / BNT, M_TOK / BMT), 256, GEMM_SMEM>>>(
        p_attn, p_wp, x, p_x1, M_TOK, D_MODEL, D_MODEL);

    rmsnorm_kernel<<<M_TOK, 256>>>(p_x1, n2, p_h);

    tgemm_kernel<2, 1><<<dim3(4 * D_MODEL / BNT, M_TOK / BMT), 256, GEMM_SMEM>>>(
        p_h, p_w1, nullptr, p_ffn, M_TOK, 4 * D_MODEL, D_MODEL);

    tgemm_kernel<1, 0><<<dim3(D_MODEL / BNT, M_TOK / BMT), 256, GEMM_SMEM>>>(
        p_ffn, p_w2, p_x1, out, M_TOK, D_MODEL, 4 * D_MODEL);
}